// round 2
// baseline (speedup 1.0000x reference)
#include <cuda_runtime.h>

// Problem constants (validated against in_sizes at launch)
#define NMAX 20000
#define EMAX 320000
#define ETMAX (NMAX + EMAX)

// ---------------- scratch (device globals; no allocation allowed) ----------
__device__ float g_h1[NMAX * 512];    // x @ W1^T
__device__ float g_out1[NMAX * 512];  // layer1 output (post bias+relu)
__device__ float g_h2[NMAX * 128];    // out1 @ W2^T
__device__ float g_out2[NMAX * 128];  // layer2 output (post bias+relu)
__device__ float g_asrc1[NMAX * 8], g_adst1[NMAX * 8];
__device__ float g_asrc2[NMAX], g_adst2[NMAX];
__device__ int g_cnt[NMAX];
__device__ int g_cursor[NMAX];
__device__ int g_rowstart[NMAX + 1];
__device__ int g_csrc[ETMAX];         // CSR (by dst) list of source nodes
__device__ float g_pooled[256 * 128];

// ---------------- init --------------------------------------------------
__global__ void init_kernel(int N) {
    int i = blockIdx.x * blockDim.x + threadIdx.x;
    if (i < N) { g_cnt[i] = 0; g_cursor[i] = 0; }
    if (i < 256 * 128) g_pooled[i] = 0.0f;
}

// ---------------- CSR build (by destination) ----------------------------
__global__ void count_kernel(const int* __restrict__ ei, int E, int N) {
    int e = blockIdx.x * blockDim.x + threadIdx.x;
    if (e >= E + N) return;
    int d = (e < E) ? ei[E + e] : (e - E);  // self loop for e >= E
    atomicAdd(&g_cnt[d], 1);
}

__global__ void scan_kernel(int N, int ET) {
    __shared__ int sums[1024];
    int tid = threadIdx.x;
    int CH = (N + 1023) >> 10;
    int base = tid * CH;
    int s = 0;
    for (int j = 0; j < CH; j++) {
        int idx = base + j;
        if (idx < N) s += g_cnt[idx];
    }
    sums[tid] = s;
    __syncthreads();
    for (int off = 1; off < 1024; off <<= 1) {
        int v = (tid >= off) ? sums[tid - off] : 0;
        __syncthreads();
        sums[tid] += v;
        __syncthreads();
    }
    int run = sums[tid] - s;  // exclusive prefix
    for (int j = 0; j < CH; j++) {
        int idx = base + j;
        if (idx < N) { g_rowstart[idx] = run; run += g_cnt[idx]; }
    }
    if (tid == 0) g_rowstart[N] = ET;
}

__global__ void scatter_kernel(const int* __restrict__ ei, int E, int N) {
    int e = blockIdx.x * blockDim.x + threadIdx.x;
    if (e >= E + N) return;
    int s, d;
    if (e < E) { s = ei[e]; d = ei[E + e]; }
    else       { s = d = e - E; }
    int pos = g_rowstart[d] + atomicAdd(&g_cursor[d], 1);
    g_csrc[pos] = s;
}

// ---------------- generic C[M,N] = A[M,K] @ B[N,K]^T (both K-major) ------
__global__ void gemm_nt_kernel(const float* __restrict__ A,
                               const float* __restrict__ B,
                               float* __restrict__ C,
                               int M, int N, int K) {
    __shared__ float As[16][68];
    __shared__ float Bs[16][68];
    const int tid = threadIdx.x;             // 256
    const int bm = blockIdx.y * 64;
    const int bn = blockIdx.x * 64;
    const int tm = (tid / 16) * 4;
    const int tn = (tid % 16) * 4;
    const int lr = tid >> 2;                 // 0..63
    const int lc = (tid & 3) * 4;            // 0,4,8,12
    float acc[4][4] = {};
    for (int k0 = 0; k0 < K; k0 += 16) {
        float4 av = make_float4(0.f, 0.f, 0.f, 0.f);
        int ar = bm + lr;
        if (ar < M) av = *(const float4*)&A[(size_t)ar * K + k0 + lc];
        As[lc + 0][lr] = av.x; As[lc + 1][lr] = av.y;
        As[lc + 2][lr] = av.z; As[lc + 3][lr] = av.w;
        float4 bv = *(const float4*)&B[(size_t)(bn + lr) * K + k0 + lc];
        Bs[lc + 0][lr] = bv.x; Bs[lc + 1][lr] = bv.y;
        Bs[lc + 2][lr] = bv.z; Bs[lc + 3][lr] = bv.w;
        __syncthreads();
#pragma unroll
        for (int k = 0; k < 16; k++) {
            float4 aa = *(const float4*)&As[k][tm];
            float4 bb = *(const float4*)&Bs[k][tn];
            acc[0][0] += aa.x * bb.x; acc[0][1] += aa.x * bb.y;
            acc[0][2] += aa.x * bb.z; acc[0][3] += aa.x * bb.w;
            acc[1][0] += aa.y * bb.x; acc[1][1] += aa.y * bb.y;
            acc[1][2] += aa.y * bb.z; acc[1][3] += aa.y * bb.w;
            acc[2][0] += aa.z * bb.x; acc[2][1] += aa.z * bb.y;
            acc[2][2] += aa.z * bb.z; acc[2][3] += aa.z * bb.w;
            acc[3][0] += aa.w * bb.x; acc[3][1] += aa.w * bb.y;
            acc[3][2] += aa.w * bb.z; acc[3][3] += aa.w * bb.w;
        }
        __syncthreads();
    }
#pragma unroll
    for (int i = 0; i < 4; i++) {
        int r = bm + tm + i;
        if (r < M) {
            float4 o = make_float4(acc[i][0], acc[i][1], acc[i][2], acc[i][3]);
            *(float4*)&C[(size_t)r * N + bn + tn] = o;
        }
    }
}

// ---------------- attention logit projections ----------------------------
// layer1: a_src[n,h] = dot(h1[n, h*64 : h*64+64], att_src1[h]); warp per (n,h)
__global__ void attn1_kernel(const float* __restrict__ att_s,
                             const float* __restrict__ att_d, int N) {
    int gt = blockIdx.x * blockDim.x + threadIdx.x;
    int warp = gt >> 5, lane = gt & 31;
    if (warp >= N * 8) return;
    int h = warp & 7;
    const float* hp = &g_h1[(size_t)warp * 64];  // n*512 + h*64 == warp*64
    float2 v  = *(const float2*)&hp[lane * 2];
    float2 vs = *(const float2*)&att_s[h * 64 + lane * 2];
    float2 vd = *(const float2*)&att_d[h * 64 + lane * 2];
    float ss = v.x * vs.x + v.y * vs.y;
    float sd = v.x * vd.x + v.y * vd.y;
#pragma unroll
    for (int o = 16; o > 0; o >>= 1) {
        ss += __shfl_xor_sync(0xffffffffu, ss, o);
        sd += __shfl_xor_sync(0xffffffffu, sd, o);
    }
    if (lane == 0) { g_asrc1[warp] = ss; g_adst1[warp] = sd; }
}

// layer2 (H=1, C=128): warp per node
__global__ void attn2_kernel(const float* __restrict__ att_s,
                             const float* __restrict__ att_d, int N) {
    int gt = blockIdx.x * blockDim.x + threadIdx.x;
    int n = gt >> 5, lane = gt & 31;
    if (n >= N) return;
    float4 v  = *(const float4*)&g_h2[(size_t)n * 128 + lane * 4];
    float4 vs = *(const float4*)&att_s[lane * 4];
    float4 vd = *(const float4*)&att_d[lane * 4];
    float ss = v.x * vs.x + v.y * vs.y + v.z * vs.z + v.w * vs.w;
    float sd = v.x * vd.x + v.y * vd.y + v.z * vd.z + v.w * vd.w;
#pragma unroll
    for (int o = 16; o > 0; o >>= 1) {
        ss += __shfl_xor_sync(0xffffffffu, ss, o);
        sd += __shfl_xor_sync(0xffffffffu, sd, o);
    }
    if (lane == 0) { g_asrc2[n] = ss; g_adst2[n] = sd; }
}

// ---------------- fused segment-softmax + aggregation --------------------
// layer1: one 128-thread block per dst node; thread t owns floats [4t,4t+4),
// head h = t/16. Two passes over the incoming-edge list: max, then exp+acc.
__global__ void gatagg1_kernel(const float* __restrict__ b1, int N) {
    int n = blockIdx.x;
    int t = threadIdx.x;
    int h = t >> 4;
    int start = g_rowstart[n], end = g_rowstart[n + 1];
    float adst = g_adst1[n * 8 + h];
    float m = -1e30f;
    for (int i = start; i < end; i++) {
        int s = g_csrc[i];
        float v = g_asrc1[s * 8 + h] + adst;
        v = (v >= 0.f) ? v : 0.2f * v;
        m = fmaxf(m, v);
    }
    float den = 0.f;
    float4 acc = make_float4(0.f, 0.f, 0.f, 0.f);
    for (int i = start; i < end; i++) {
        int s = g_csrc[i];
        float v = g_asrc1[s * 8 + h] + adst;
        v = (v >= 0.f) ? v : 0.2f * v;
        float ex = __expf(v - m);
        den += ex;
        float4 hv = *(const float4*)&g_h1[(size_t)s * 512 + t * 4];
        acc.x += ex * hv.x; acc.y += ex * hv.y;
        acc.z += ex * hv.z; acc.w += ex * hv.w;
    }
    float inv = 1.f / (den + 1e-16f);
    float4 bb = *(const float4*)&b1[t * 4];
    float4 o;
    o.x = fmaxf(fmaf(acc.x, inv, bb.x), 0.f);
    o.y = fmaxf(fmaf(acc.y, inv, bb.y), 0.f);
    o.z = fmaxf(fmaf(acc.z, inv, bb.z), 0.f);
    o.w = fmaxf(fmaf(acc.w, inv, bb.w), 0.f);
    *(float4*)&g_out1[(size_t)n * 512 + t * 4] = o;
}

// layer2 (H=1): one warp per dst node, 4 warps per block
__global__ void gatagg2_kernel(const float* __restrict__ b2, int N) {
    int n = blockIdx.x * 4 + (threadIdx.x >> 5);
    if (n >= N) return;
    int lane = threadIdx.x & 31;
    int start = g_rowstart[n], end = g_rowstart[n + 1];
    float adst = g_adst2[n];
    float m = -1e30f;
    for (int i = start; i < end; i++) {
        float v = g_asrc2[g_csrc[i]] + adst;
        v = (v >= 0.f) ? v : 0.2f * v;
        m = fmaxf(m, v);
    }
    float den = 0.f;
    float4 acc = make_float4(0.f, 0.f, 0.f, 0.f);
    for (int i = start; i < end; i++) {
        int s = g_csrc[i];
        float v = g_asrc2[s] + adst;
        v = (v >= 0.f) ? v : 0.2f * v;
        float ex = __expf(v - m);
        den += ex;
        float4 hv = *(const float4*)&g_h2[(size_t)s * 128 + lane * 4];
        acc.x += ex * hv.x; acc.y += ex * hv.y;
        acc.z += ex * hv.z; acc.w += ex * hv.w;
    }
    float inv = 1.f / (den + 1e-16f);
    float4 bb = *(const float4*)&b2[lane * 4];
    float4 o;
    o.x = fmaxf(fmaf(acc.x, inv, bb.x), 0.f);
    o.y = fmaxf(fmaf(acc.y, inv, bb.y), 0.f);
    o.z = fmaxf(fmaf(acc.z, inv, bb.z), 0.f);
    o.w = fmaxf(fmaf(acc.w, inv, bb.w), 0.f);
    *(float4*)&g_out2[(size_t)n * 128 + lane * 4] = o;
}

// ---------------- attention pooling over graphs --------------------------
__global__ void pool_kernel(const int* __restrict__ batch,
                            const float* __restrict__ wA, const float* __restrict__ bA,
                            const float* __restrict__ wM, const float* __restrict__ bM,
                            int N) {
    int n = blockIdx.x;
    int t = threadIdx.x;  // 128
    float v = g_out2[(size_t)n * 128 + t];
    __shared__ float s1[128], s2[128];
    s1[t] = v * wA[t];
    s2[t] = v * wM[t];
    __syncthreads();
    for (int off = 64; off > 0; off >>= 1) {
        if (t < off) { s1[t] += s1[t + off]; s2[t] += s2[t + off]; }
        __syncthreads();
    }
    __shared__ float wsh;
    if (t == 0) {
        float at = s1[0] + bA[0];
        float mk = 1.f / (1.f + __expf(-(s2[0] + bM[0])));
        wsh = at * mk;
    }
    __syncthreads();
    atomicAdd(&g_pooled[batch[n] * 128 + t], v * wsh);
}

// ---------------- final projection [256,128] @ [2,128]^T + b -------------
__global__ void final_kernel(const float* __restrict__ Wo,
                             const float* __restrict__ bo,
                             float* __restrict__ out) {
    int i = threadIdx.x;  // 512
    int g = i >> 1, o = i & 1;
    float s = 0.f;
#pragma unroll 4
    for (int k = 0; k < 128; k++)
        s += g_pooled[g * 128 + k] * Wo[o * 128 + k];
    out[i] = s + bo[o];
}

// ---------------- launch --------------------------------------------------
extern "C" void kernel_launch(void* const* d_in, const int* in_sizes, int n_in,
                              void* d_out, int out_size) {
    const float* x      = (const float*)d_in[0];
    const int*   ei     = (const int*)d_in[1];
    const int*   batch  = (const int*)d_in[2];
    const float* W1     = (const float*)d_in[3];
    const float* as1    = (const float*)d_in[4];
    const float* ad1    = (const float*)d_in[5];
    const float* b1     = (const float*)d_in[6];
    const float* W2     = (const float*)d_in[7];
    const float* as2    = (const float*)d_in[8];
    const float* ad2    = (const float*)d_in[9];
    const float* b2     = (const float*)d_in[10];
    const float* w_attn = (const float*)d_in[11];
    const float* b_attn = (const float*)d_in[12];
    const float* w_mask = (const float*)d_in[13];
    const float* b_mask = (const float*)d_in[14];
    const float* W_out  = (const float*)d_in[15];
    const float* b_out  = (const float*)d_in[16];
    float* out = (float*)d_out;

    int N = in_sizes[0] / 128;
    int E = in_sizes[1] / 2;
    int ET = N + E;

    float *p_h1, *p_out1, *p_h2;
    cudaGetSymbolAddress((void**)&p_h1, g_h1);
    cudaGetSymbolAddress((void**)&p_out1, g_out1);
    cudaGetSymbolAddress((void**)&p_h2, g_h2);

    int init_n = (N > 256 * 128) ? N : 256 * 128;
    init_kernel<<<(init_n + 255) / 256, 256>>>(N);

    count_kernel<<<(ET + 255) / 256, 256>>>(ei, E, N);
    scan_kernel<<<1, 1024>>>(N, ET);
    scatter_kernel<<<(ET + 255) / 256, 256>>>(ei, E, N);

    // layer 1
    {
        dim3 grid(512 / 64, (N + 63) / 64);
        gemm_nt_kernel<<<grid, 256>>>(x, W1, p_h1, N, 512, 128);
    }
    attn1_kernel<<<(N * 8 * 32 + 255) / 256, 256>>>(as1, ad1, N);
    gatagg1_kernel<<<N, 128>>>(b1, N);

    // layer 2
    {
        dim3 grid(128 / 64, (N + 63) / 64);
        gemm_nt_kernel<<<grid, 256>>>(p_out1, W2, p_h2, N, 128, 512);
    }
    attn2_kernel<<<(N * 32 + 255) / 256, 256>>>(as2, ad2, N);
    gatagg2_kernel<<<(N + 3) / 4, 128>>>(b2, N);

    // pooling + readout
    pool_kernel<<<N, 128>>>(batch, w_attn, b_attn, w_mask, b_mask, N);
    final_kernel<<<1, 512>>>(W_out, b_out, out);
}

// round 4
// speedup vs baseline: 1.1941x; 1.1941x over previous
#include <cuda_runtime.h>
#include <cuda_bf16.h>
#include <cstdint>

#define NMAX 20000
#define EMAX 320000
#define ETMAX (NMAX + EMAX)

// ---------------- scratch (device globals) --------------------------------
__device__ float g_h1[NMAX * 512];                 // x @ W1^T (fp32)
__device__ float g_h2[NMAX * 128];                 // out1 @ W2^T
__device__ float g_out2[NMAX * 128];               // layer2 output
__device__ __nv_bfloat16 g_xhi[NMAX * 128], g_xlo[NMAX * 128];
__device__ __nv_bfloat16 g_o1hi[NMAX * 512], g_o1lo[NMAX * 512];
__device__ __nv_bfloat16 g_w1hi[512 * 128], g_w1lo[512 * 128];
__device__ __nv_bfloat16 g_w2hi[128 * 512], g_w2lo[128 * 512];
__device__ float g_asrc1[NMAX * 8], g_adst1[NMAX * 8];
__device__ float g_asrc2[NMAX], g_adst2[NMAX];
__device__ int g_cnt[NMAX];
__device__ int g_cursor[NMAX];
__device__ int g_rowstart[NMAX + 1];
__device__ int g_csrc[ETMAX];
__device__ float g_pooled[256 * 128];

// ---------------- init / CSR ----------------------------------------------
__global__ void init_kernel(int N) {
    int i = blockIdx.x * blockDim.x + threadIdx.x;
    if (i < N) { g_cnt[i] = 0; g_cursor[i] = 0; }
    if (i < 256 * 128) g_pooled[i] = 0.0f;
}
__global__ void count_kernel(const int* __restrict__ ei, int E, int N) {
    int e = blockIdx.x * blockDim.x + threadIdx.x;
    if (e >= E + N) return;
    int d = (e < E) ? ei[E + e] : (e - E);
    atomicAdd(&g_cnt[d], 1);
}
__global__ void scan_kernel(int N, int ET) {
    __shared__ int sums[1024];
    int tid = threadIdx.x;
    int CH = (N + 1023) >> 10;
    int base = tid * CH, s = 0;
    for (int j = 0; j < CH; j++) { int idx = base + j; if (idx < N) s += g_cnt[idx]; }
    sums[tid] = s;
    __syncthreads();
    for (int off = 1; off < 1024; off <<= 1) {
        int v = (tid >= off) ? sums[tid - off] : 0;
        __syncthreads();
        sums[tid] += v;
        __syncthreads();
    }
    int run = sums[tid] - s;
    for (int j = 0; j < CH; j++) {
        int idx = base + j;
        if (idx < N) { g_rowstart[idx] = run; run += g_cnt[idx]; }
    }
    if (tid == 0) g_rowstart[N] = ET;
}
__global__ void scatter_kernel(const int* __restrict__ ei, int E, int N) {
    int e = blockIdx.x * blockDim.x + threadIdx.x;
    if (e >= E + N) return;
    int s, d;
    if (e < E) { s = ei[e]; d = ei[E + e]; }
    else       { s = d = e - E; }
    int pos = g_rowstart[d] + atomicAdd(&g_cursor[d], 1);
    g_csrc[pos] = s;
}

// ---------------- fp32 -> bf16 hi/lo split ---------------------------------
__global__ void split_kernel(const float* __restrict__ src,
                             __nv_bfloat16* __restrict__ hi,
                             __nv_bfloat16* __restrict__ lo, int n) {
    int i = blockIdx.x * blockDim.x + threadIdx.x;
    if (i >= n) return;
    float v = src[i];
    __nv_bfloat16 h = __float2bfloat16(v);
    hi[i] = h;
    lo[i] = __float2bfloat16(v - __bfloat162float(h));
}

// ---------------- bf16x3 HMMA GEMM: C[M,Ntot] = A @ B^T --------------------
// A (hi/lo): [M,K] bf16 row-major. B (hi/lo): [Ntot,K] bf16 row-major.
// CTA tile 128x128, 8 warps (warp tile 32x64), k-step 16.
// smem tiles padded to 24 halves/row (48B) -> conflict-free ldmatrix.
#define TSTR 24
__global__ void __launch_bounds__(256, 2)
gemm_bf16x3_kernel(const __nv_bfloat16* __restrict__ Ahi,
                   const __nv_bfloat16* __restrict__ Alo,
                   const __nv_bfloat16* __restrict__ Bhi,
                   const __nv_bfloat16* __restrict__ Blo,
                   float* __restrict__ C, int M, int Ntot, int K) {
    __shared__ __nv_bfloat16 sAh[128 * TSTR], sAl[128 * TSTR];
    __shared__ __nv_bfloat16 sBh[128 * TSTR], sBl[128 * TSTR];

    const int tid = threadIdx.x;
    const int wid = tid >> 5, lane = tid & 31;
    const int bm = blockIdx.y * 128;
    const int bn = blockIdx.x * 128;
    const int wm = (wid & 3) * 32;       // warp M offset in tile
    const int wn = (wid >> 2) * 64;      // warp N offset in tile

    // gmem->smem: thread (row=tid>>1, part=tid&1) stores 8 halves (16B)
    const int srow = tid >> 1;
    const int spart = tid & 1;
    const int arow = bm + srow;
    const bool avalid = arow < M;
    const int brow = bn + srow;
    const uint32_t sw = srow * TSTR + spart * 8;   // halves index into tile

    // ldmatrix source offsets (halves)
    const int a_r = lane & 15;
    const int a_c = (lane >> 4) * 8;
    const int b_r = lane & 7;
    const int b_c = ((lane >> 3) & 1) * 8;

    const int g = lane >> 2;             // fragment row group
    const int tg = lane & 3;

    float acc[2][8][4];
#pragma unroll
    for (int mi = 0; mi < 2; mi++)
#pragma unroll
        for (int ni = 0; ni < 8; ni++)
#pragma unroll
            for (int j = 0; j < 4; j++) acc[mi][ni][j] = 0.f;

    const uint4 z4 = make_uint4(0u, 0u, 0u, 0u);

    for (int k0 = 0; k0 < K; k0 += 16) {
        // load tiles
        {
            const size_t ao = (size_t)arow * K + k0 + spart * 8;
            const size_t bo = (size_t)brow * K + k0 + spart * 8;
            uint4 th = z4, tl = z4;
            if (avalid) {
                th = *(const uint4*)(Ahi + ao);
                tl = *(const uint4*)(Alo + ao);
            }
            *(uint4*)&sAh[sw] = th;
            *(uint4*)&sAl[sw] = tl;
            *(uint4*)&sBh[sw] = *(const uint4*)(Bhi + bo);
            *(uint4*)&sBl[sw] = *(const uint4*)(Blo + bo);
        }
        __syncthreads();

        // A fragments (hi & lo) for both m-tiles
        uint32_t ah[2][4], al[2][4];
#pragma unroll
        for (int mi = 0; mi < 2; mi++) {
            uint32_t offh = (uint32_t)((wm + mi * 16 + a_r) * TSTR + a_c) * 2;
            uint32_t ad;
            asm("{ .reg .u64 t; cvta.to.shared.u64 t, %1; cvt.u32.u64 %0, t; }"
                : "=r"(ad) : "l"((const char*)sAh + offh));
            asm volatile("ldmatrix.sync.aligned.m8n8.x4.shared.b16 {%0,%1,%2,%3}, [%4];"
                         : "=r"(ah[mi][0]), "=r"(ah[mi][1]), "=r"(ah[mi][2]), "=r"(ah[mi][3])
                         : "r"(ad));
            asm("{ .reg .u64 t; cvta.to.shared.u64 t, %1; cvt.u32.u64 %0, t; }"
                : "=r"(ad) : "l"((const char*)sAl + offh));
            asm volatile("ldmatrix.sync.aligned.m8n8.x4.shared.b16 {%0,%1,%2,%3}, [%4];"
                         : "=r"(al[mi][0]), "=r"(al[mi][1]), "=r"(al[mi][2]), "=r"(al[mi][3])
                         : "r"(ad));
        }

#pragma unroll
        for (int ni = 0; ni < 8; ni++) {
            uint32_t off = (uint32_t)((wn + ni * 8 + b_r) * TSTR + b_c) * 2;
            uint32_t bh0, bh1, bl0, bl1, ad;
            asm("{ .reg .u64 t; cvta.to.shared.u64 t, %1; cvt.u32.u64 %0, t; }"
                : "=r"(ad) : "l"((const char*)sBh + off));
            asm volatile("ldmatrix.sync.aligned.m8n8.x2.shared.b16 {%0,%1}, [%2];"
                         : "=r"(bh0), "=r"(bh1) : "r"(ad));
            asm("{ .reg .u64 t; cvta.to.shared.u64 t, %1; cvt.u32.u64 %0, t; }"
                : "=r"(ad) : "l"((const char*)sBl + off));
            asm volatile("ldmatrix.sync.aligned.m8n8.x2.shared.b16 {%0,%1}, [%2];"
                         : "=r"(bl0), "=r"(bl1) : "r"(ad));
#pragma unroll
            for (int mi = 0; mi < 2; mi++) {
                float* c = acc[mi][ni];
                asm volatile(
                    "mma.sync.aligned.m16n8k16.row.col.f32.bf16.bf16.f32 "
                    "{%0,%1,%2,%3}, {%4,%5,%6,%7}, {%8,%9}, {%0,%1,%2,%3};"
                    : "+f"(c[0]), "+f"(c[1]), "+f"(c[2]), "+f"(c[3])
                    : "r"(ah[mi][0]), "r"(ah[mi][1]), "r"(ah[mi][2]), "r"(ah[mi][3]),
                      "r"(bh0), "r"(bh1));
                asm volatile(
                    "mma.sync.aligned.m16n8k16.row.col.f32.bf16.bf16.f32 "
                    "{%0,%1,%2,%3}, {%4,%5,%6,%7}, {%8,%9}, {%0,%1,%2,%3};"
                    : "+f"(c[0]), "+f"(c[1]), "+f"(c[2]), "+f"(c[3])
                    : "r"(ah[mi][0]), "r"(ah[mi][1]), "r"(ah[mi][2]), "r"(ah[mi][3]),
                      "r"(bl0), "r"(bl1));
                asm volatile(
                    "mma.sync.aligned.m16n8k16.row.col.f32.bf16.bf16.f32 "
                    "{%0,%1,%2,%3}, {%4,%5,%6,%7}, {%8,%9}, {%0,%1,%2,%3};"
                    : "+f"(c[0]), "+f"(c[1]), "+f"(c[2]), "+f"(c[3])
                    : "r"(al[mi][0]), "r"(al[mi][1]), "r"(al[mi][2]), "r"(al[mi][3]),
                      "r"(bh0), "r"(bh1));
            }
        }
        __syncthreads();
    }

    // epilogue
#pragma unroll
    for (int mi = 0; mi < 2; mi++) {
        int r0 = bm + wm + mi * 16 + g;
        int r1 = r0 + 8;
#pragma unroll
        for (int ni = 0; ni < 8; ni++) {
            int col = bn + wn + ni * 8 + tg * 2;
            if (r0 < M)
                *(float2*)&C[(size_t)r0 * Ntot + col] = make_float2(acc[mi][ni][0], acc[mi][ni][1]);
            if (r1 < M)
                *(float2*)&C[(size_t)r1 * Ntot + col] = make_float2(acc[mi][ni][2], acc[mi][ni][3]);
        }
    }
}

// ---------------- attention logit projections ------------------------------
__global__ void attn1_kernel(const float* __restrict__ att_s,
                             const float* __restrict__ att_d, int N) {
    int gt = blockIdx.x * blockDim.x + threadIdx.x;
    int warp = gt >> 5, lane = gt & 31;
    if (warp >= N * 8) return;
    int h = warp & 7;
    const float* hp = &g_h1[(size_t)warp * 64];
    float2 v  = *(const float2*)&hp[lane * 2];
    float2 vs = *(const float2*)&att_s[h * 64 + lane * 2];
    float2 vd = *(const float2*)&att_d[h * 64 + lane * 2];
    float ss = v.x * vs.x + v.y * vs.y;
    float sd = v.x * vd.x + v.y * vd.y;
#pragma unroll
    for (int o = 16; o > 0; o >>= 1) {
        ss += __shfl_xor_sync(0xffffffffu, ss, o);
        sd += __shfl_xor_sync(0xffffffffu, sd, o);
    }
    if (lane == 0) { g_asrc1[warp] = ss; g_adst1[warp] = sd; }
}
__global__ void attn2_kernel(const float* __restrict__ att_s,
                             const float* __restrict__ att_d, int N) {
    int gt = blockIdx.x * blockDim.x + threadIdx.x;
    int n = gt >> 5, lane = gt & 31;
    if (n >= N) return;
    float4 v  = *(const float4*)&g_h2[(size_t)n * 128 + lane * 4];
    float4 vs = *(const float4*)&att_s[lane * 4];
    float4 vd = *(const float4*)&att_d[lane * 4];
    float ss = v.x * vs.x + v.y * vs.y + v.z * vs.z + v.w * vs.w;
    float sd = v.x * vd.x + v.y * vd.y + v.z * vd.z + v.w * vd.w;
#pragma unroll
    for (int o = 16; o > 0; o >>= 1) {
        ss += __shfl_xor_sync(0xffffffffu, ss, o);
        sd += __shfl_xor_sync(0xffffffffu, sd, o);
    }
    if (lane == 0) { g_asrc2[n] = ss; g_adst2[n] = sd; }
}

// ---------------- fused segment-softmax + aggregation ----------------------
__global__ void gatagg1_kernel(const float* __restrict__ b1, int N) {
    int n = blockIdx.x;
    int t = threadIdx.x;
    int h = t >> 4;
    int start = g_rowstart[n], end = g_rowstart[n + 1];
    float adst = g_adst1[n * 8 + h];
    float m = -1e30f;
    for (int i = start; i < end; i++) {
        int s = g_csrc[i];
        float v = g_asrc1[s * 8 + h] + adst;
        v = (v >= 0.f) ? v : 0.2f * v;
        m = fmaxf(m, v);
    }
    float den = 0.f;
    float4 acc = make_float4(0.f, 0.f, 0.f, 0.f);
    for (int i = start; i < end; i++) {
        int s = g_csrc[i];
        float v = g_asrc1[s * 8 + h] + adst;
        v = (v >= 0.f) ? v : 0.2f * v;
        float ex = __expf(v - m);
        den += ex;
        float4 hv = *(const float4*)&g_h1[(size_t)s * 512 + t * 4];
        acc.x += ex * hv.x; acc.y += ex * hv.y;
        acc.z += ex * hv.z; acc.w += ex * hv.w;
    }
    float inv = 1.f / (den + 1e-16f);
    float4 bb = *(const float4*)&b1[t * 4];
    float o[4];
    o[0] = fmaxf(fmaf(acc.x, inv, bb.x), 0.f);
    o[1] = fmaxf(fmaf(acc.y, inv, bb.y), 0.f);
    o[2] = fmaxf(fmaf(acc.z, inv, bb.z), 0.f);
    o[3] = fmaxf(fmaf(acc.w, inv, bb.w), 0.f);
    uint32_t ph[2], pl[2];
#pragma unroll
    for (int k = 0; k < 2; k++) {
        __nv_bfloat16 h0 = __float2bfloat16(o[2 * k]);
        __nv_bfloat16 h1v = __float2bfloat16(o[2 * k + 1]);
        __nv_bfloat16 l0 = __float2bfloat16(o[2 * k] - __bfloat162float(h0));
        __nv_bfloat16 l1 = __float2bfloat16(o[2 * k + 1] - __bfloat162float(h1v));
        ph[k] = (uint32_t)__bfloat16_as_ushort(h0) | ((uint32_t)__bfloat16_as_ushort(h1v) << 16);
        pl[k] = (uint32_t)__bfloat16_as_ushort(l0) | ((uint32_t)__bfloat16_as_ushort(l1) << 16);
    }
    size_t o4 = (size_t)n * 512 + t * 4;
    *(uint2*)&g_o1hi[o4] = make_uint2(ph[0], ph[1]);
    *(uint2*)&g_o1lo[o4] = make_uint2(pl[0], pl[1]);
}

__global__ void gatagg2_kernel(const float* __restrict__ b2, int N) {
    int n = blockIdx.x * 4 + (threadIdx.x >> 5);
    if (n >= N) return;
    int lane = threadIdx.x & 31;
    int start = g_rowstart[n], end = g_rowstart[n + 1];
    float adst = g_adst2[n];
    float m = -1e30f;
    for (int i = start; i < end; i++) {
        float v = g_asrc2[g_csrc[i]] + adst;
        v = (v >= 0.f) ? v : 0.2f * v;
        m = fmaxf(m, v);
    }
    float den = 0.f;
    float4 acc = make_float4(0.f, 0.f, 0.f, 0.f);
    for (int i = start; i < end; i++) {
        int s = g_csrc[i];
        float v = g_asrc2[s] + adst;
        v = (v >= 0.f) ? v : 0.2f * v;
        float ex = __expf(v - m);
        den += ex;
        float4 hv = *(const float4*)&g_h2[(size_t)s * 128 + lane * 4];
        acc.x += ex * hv.x; acc.y += ex * hv.y;
        acc.z += ex * hv.z; acc.w += ex * hv.w;
    }
    float inv = 1.f / (den + 1e-16f);
    float4 bb = *(const float4*)&b2[lane * 4];
    float4 o;
    o.x = fmaxf(fmaf(acc.x, inv, bb.x), 0.f);
    o.y = fmaxf(fmaf(acc.y, inv, bb.y), 0.f);
    o.z = fmaxf(fmaf(acc.z, inv, bb.z), 0.f);
    o.w = fmaxf(fmaf(acc.w, inv, bb.w), 0.f);
    *(float4*)&g_out2[(size_t)n * 128 + lane * 4] = o;
}

// ---------------- pooling + readout ----------------------------------------
__global__ void pool_kernel(const int* __restrict__ batch,
                            const float* __restrict__ wA, const float* __restrict__ bA,
                            const float* __restrict__ wM, const float* __restrict__ bM,
                            int N) {
    int n = blockIdx.x;
    int t = threadIdx.x;
    float v = g_out2[(size_t)n * 128 + t];
    __shared__ float s1[128], s2[128];
    s1[t] = v * wA[t];
    s2[t] = v * wM[t];
    __syncthreads();
    for (int off = 64; off > 0; off >>= 1) {
        if (t < off) { s1[t] += s1[t + off]; s2[t] += s2[t + off]; }
        __syncthreads();
    }
    __shared__ float wsh;
    if (t == 0) {
        float at = s1[0] + bA[0];
        float mk = 1.f / (1.f + __expf(-(s2[0] + bM[0])));
        wsh = at * mk;
    }
    __syncthreads();
    atomicAdd(&g_pooled[batch[n] * 128 + t], v * wsh);
}
__global__ void final_kernel(const float* __restrict__ Wo,
                             const float* __restrict__ bo,
                             float* __restrict__ out) {
    int i = threadIdx.x;
    int g = i >> 1, o = i & 1;
    float s = 0.f;
#pragma unroll 4
    for (int k = 0; k < 128; k++)
        s += g_pooled[g * 128 + k] * Wo[o * 128 + k];
    out[i] = s + bo[o];
}

// ---------------- launch ----------------------------------------------------
extern "C" void kernel_launch(void* const* d_in, const int* in_sizes, int n_in,
                              void* d_out, int out_size) {
    const float* x      = (const float*)d_in[0];
    const int*   ei     = (const int*)d_in[1];
    const int*   batch  = (const int*)d_in[2];
    const float* W1     = (const float*)d_in[3];
    const float* as1    = (const float*)d_in[4];
    const float* ad1    = (const float*)d_in[5];
    const float* b1     = (const float*)d_in[6];
    const float* W2     = (const float*)d_in[7];
    const float* as2    = (const float*)d_in[8];
    const float* ad2    = (const float*)d_in[9];
    const float* b2     = (const float*)d_in[10];
    const float* w_attn = (const float*)d_in[11];
    const float* b_attn = (const float*)d_in[12];
    const float* w_mask = (const float*)d_in[13];
    const float* b_mask = (const float*)d_in[14];
    const float* W_out  = (const float*)d_in[15];
    const float* b_out  = (const float*)d_in[16];
    float* out = (float*)d_out;

    int N = in_sizes[0] / 128;
    int E = in_sizes[1] / 2;
    int ET = N + E;

    float *p_h1, *p_h2;
    __nv_bfloat16 *p_xhi, *p_xlo, *p_o1hi, *p_o1lo, *p_w1hi, *p_w1lo, *p_w2hi, *p_w2lo;
    cudaGetSymbolAddress((void**)&p_h1, g_h1);
    cudaGetSymbolAddress((void**)&p_h2, g_h2);
    cudaGetSymbolAddress((void**)&p_xhi, g_xhi);
    cudaGetSymbolAddress((void**)&p_xlo, g_xlo);
    cudaGetSymbolAddress((void**)&p_o1hi, g_o1hi);
    cudaGetSymbolAddress((void**)&p_o1lo, g_o1lo);
    cudaGetSymbolAddress((void**)&p_w1hi, g_w1hi);
    cudaGetSymbolAddress((void**)&p_w1lo, g_w1lo);
    cudaGetSymbolAddress((void**)&p_w2hi, g_w2hi);
    cudaGetSymbolAddress((void**)&p_w2lo, g_w2lo);

    int init_n = (N > 256 * 128) ? N : 256 * 128;
    init_kernel<<<(init_n + 255) / 256, 256>>>(N);

    count_kernel<<<(ET + 255) / 256, 256>>>(ei, E, N);
    scan_kernel<<<1, 1024>>>(N, ET);
    scatter_kernel<<<(ET + 255) / 256, 256>>>(ei, E, N);

    split_kernel<<<(N * 128 + 255) / 256, 256>>>(x, p_xhi, p_xlo, N * 128);
    split_kernel<<<(512 * 128 + 255) / 256, 256>>>(W1, p_w1hi, p_w1lo, 512 * 128);
    split_kernel<<<(128 * 512 + 255) / 256, 256>>>(W2, p_w2hi, p_w2lo, 128 * 512);

    int mtiles = (N + 127) / 128;

    // layer 1: h1[N,512] = x[N,128] @ W1[512,128]^T
    {
        dim3 grid(4, mtiles);
        gemm_bf16x3_kernel<<<grid, 256>>>(p_xhi, p_xlo, p_w1hi, p_w1lo, p_h1, N, 512, 128);
    }
    attn1_kernel<<<(N * 8 * 32 + 255) / 256, 256>>>(as1, ad1, N);
    gatagg1_kernel<<<N, 128>>>(b1, N);

    // layer 2: h2[N,128] = out1[N,512] @ W2[128,512]^T
    {
        dim3 grid(1, mtiles);
        gemm_bf16x3_kernel<<<grid, 256>>>(p_o1hi, p_o1lo, p_w2hi, p_w2lo, p_h2, N, 128, 512);
    }
    attn2_kernel<<<(N * 32 + 255) / 256, 256>>>(as2, ad2, N);
    gatagg2_kernel<<<(N + 3) / 4, 128>>>(b2, N);

    pool_kernel<<<N, 128>>>(batch, w_attn, b_attn, w_mask, b_mask, N);
    final_kernel<<<1, 512>>>(W_out, b_out, out);
}

// round 5
// speedup vs baseline: 1.3188x; 1.1044x over previous
#include <cuda_runtime.h>
#include <cuda_bf16.h>
#include <cstdint>

#define NMAX 20000
#define EMAX 320000
#define ETMAX (NMAX + EMAX)

// ---------------- scratch (device globals) --------------------------------
__device__ float g_h1[NMAX * 512];                 // x @ W1^T (fp32)
__device__ float g_h2[NMAX * 128];                 // out1 @ W2^T
__device__ float g_out2[NMAX * 128];               // layer2 output
__device__ __nv_bfloat16 g_xhi[NMAX * 128], g_xlo[NMAX * 128];
__device__ __nv_bfloat16 g_o1hi[NMAX * 512], g_o1lo[NMAX * 512];
__device__ __nv_bfloat16 g_w1hi[512 * 128], g_w1lo[512 * 128];
__device__ __nv_bfloat16 g_w2hi[128 * 512], g_w2lo[128 * 512];
__device__ float g_asrc1[NMAX * 8], g_adst1[NMAX * 8];
__device__ float g_asrc2[NMAX], g_adst2[NMAX];
__device__ int g_cnt[NMAX];
__device__ int g_cursor[NMAX];
__device__ int g_rowstart[NMAX + 1];
__device__ int g_csrc[ETMAX];
__device__ float g_pooled[256 * 128];

// ---------------- init / CSR ----------------------------------------------
__global__ void init_kernel(int N) {
    int i = blockIdx.x * blockDim.x + threadIdx.x;
    if (i < N) { g_cnt[i] = 0; g_cursor[i] = 0; }
    if (i < 256 * 128) g_pooled[i] = 0.0f;
}
__global__ void count_kernel(const int* __restrict__ ei, int E, int N) {
    int e = blockIdx.x * blockDim.x + threadIdx.x;
    if (e >= E + N) return;
    int d = (e < E) ? ei[E + e] : (e - E);
    atomicAdd(&g_cnt[d], 1);
}
__global__ void scan_kernel(int N, int ET) {
    __shared__ int sums[1024];
    int tid = threadIdx.x;
    int CH = (N + 1023) >> 10;
    int base = tid * CH, s = 0;
    for (int j = 0; j < CH; j++) { int idx = base + j; if (idx < N) s += g_cnt[idx]; }
    sums[tid] = s;
    __syncthreads();
    for (int off = 1; off < 1024; off <<= 1) {
        int v = (tid >= off) ? sums[tid - off] : 0;
        __syncthreads();
        sums[tid] += v;
        __syncthreads();
    }
    int run = sums[tid] - s;
    for (int j = 0; j < CH; j++) {
        int idx = base + j;
        if (idx < N) { g_rowstart[idx] = run; run += g_cnt[idx]; }
    }
    if (tid == 0) g_rowstart[N] = ET;
}
__global__ void scatter_kernel(const int* __restrict__ ei, int E, int N) {
    int e = blockIdx.x * blockDim.x + threadIdx.x;
    if (e >= E + N) return;
    int s, d;
    if (e < E) { s = ei[e]; d = ei[E + e]; }
    else       { s = d = e - E; }
    int pos = g_rowstart[d] + atomicAdd(&g_cursor[d], 1);
    g_csrc[pos] = s;
}

// ---------------- fp32 -> bf16 hi/lo split ---------------------------------
__global__ void split_kernel(const float* __restrict__ src,
                             __nv_bfloat16* __restrict__ hi,
                             __nv_bfloat16* __restrict__ lo, int n) {
    int i = blockIdx.x * blockDim.x + threadIdx.x;
    if (i >= n) return;
    float v = src[i];
    __nv_bfloat16 h = __float2bfloat16(v);
    hi[i] = h;
    lo[i] = __float2bfloat16(v - __bfloat162float(h));
}

// ---------------- bf16x3 HMMA GEMM + fused attention projections ----------
// C[M,Ntot] = A @ B^T. Also computes aS[r,h]=dot(C[r,head h], attS[h]),
// aD likewise. Head width hw = Ntot/H (64 or 128).
#define TSTR 24
__global__ void __launch_bounds__(256, 2)
gemm_bf16x3_kernel(const __nv_bfloat16* __restrict__ Ahi,
                   const __nv_bfloat16* __restrict__ Alo,
                   const __nv_bfloat16* __restrict__ Bhi,
                   const __nv_bfloat16* __restrict__ Blo,
                   float* __restrict__ C, int M, int Ntot, int K,
                   const float* __restrict__ attS, const float* __restrict__ attD,
                   float* __restrict__ aS, float* __restrict__ aD, int H) {
    __shared__ __nv_bfloat16 sAh[128 * TSTR], sAl[128 * TSTR];
    __shared__ __nv_bfloat16 sBh[128 * TSTR], sBl[128 * TSTR];
    __shared__ float redA[2][128], redD[2][128];

    const int tid = threadIdx.x;
    const int wid = tid >> 5, lane = tid & 31;
    const int bm = blockIdx.y * 128;
    const int bn = blockIdx.x * 128;
    const int wm = (wid & 3) * 32;
    const int wn = (wid >> 2) * 64;

    const int srow = tid >> 1;
    const int spart = tid & 1;
    const int arow = bm + srow;
    const bool avalid = arow < M;
    const int brow = bn + srow;
    const uint32_t sw = srow * TSTR + spart * 8;

    const int a_r = lane & 15;
    const int a_c = (lane >> 4) * 8;
    const int b_r = lane & 7;
    const int b_c = ((lane >> 3) & 1) * 8;

    const int g = lane >> 2;
    const int tg = lane & 3;

    float acc[2][8][4];
#pragma unroll
    for (int mi = 0; mi < 2; mi++)
#pragma unroll
        for (int ni = 0; ni < 8; ni++)
#pragma unroll
            for (int j = 0; j < 4; j++) acc[mi][ni][j] = 0.f;

    const uint4 z4 = make_uint4(0u, 0u, 0u, 0u);

    for (int k0 = 0; k0 < K; k0 += 16) {
        {
            const size_t ao = (size_t)arow * K + k0 + spart * 8;
            const size_t bo = (size_t)brow * K + k0 + spart * 8;
            uint4 th = z4, tl = z4;
            if (avalid) {
                th = *(const uint4*)(Ahi + ao);
                tl = *(const uint4*)(Alo + ao);
            }
            *(uint4*)&sAh[sw] = th;
            *(uint4*)&sAl[sw] = tl;
            *(uint4*)&sBh[sw] = *(const uint4*)(Bhi + bo);
            *(uint4*)&sBl[sw] = *(const uint4*)(Blo + bo);
        }
        __syncthreads();

        uint32_t ah[2][4], al[2][4];
#pragma unroll
        for (int mi = 0; mi < 2; mi++) {
            uint32_t offh = (uint32_t)((wm + mi * 16 + a_r) * TSTR + a_c) * 2;
            uint32_t ad;
            asm("{ .reg .u64 t; cvta.to.shared.u64 t, %1; cvt.u32.u64 %0, t; }"
                : "=r"(ad) : "l"((const char*)sAh + offh));
            asm volatile("ldmatrix.sync.aligned.m8n8.x4.shared.b16 {%0,%1,%2,%3}, [%4];"
                         : "=r"(ah[mi][0]), "=r"(ah[mi][1]), "=r"(ah[mi][2]), "=r"(ah[mi][3])
                         : "r"(ad));
            asm("{ .reg .u64 t; cvta.to.shared.u64 t, %1; cvt.u32.u64 %0, t; }"
                : "=r"(ad) : "l"((const char*)sAl + offh));
            asm volatile("ldmatrix.sync.aligned.m8n8.x4.shared.b16 {%0,%1,%2,%3}, [%4];"
                         : "=r"(al[mi][0]), "=r"(al[mi][1]), "=r"(al[mi][2]), "=r"(al[mi][3])
                         : "r"(ad));
        }

#pragma unroll
        for (int ni = 0; ni < 8; ni++) {
            uint32_t off = (uint32_t)((wn + ni * 8 + b_r) * TSTR + b_c) * 2;
            uint32_t bh0, bh1, bl0, bl1, ad;
            asm("{ .reg .u64 t; cvta.to.shared.u64 t, %1; cvt.u32.u64 %0, t; }"
                : "=r"(ad) : "l"((const char*)sBh + off));
            asm volatile("ldmatrix.sync.aligned.m8n8.x2.shared.b16 {%0,%1}, [%2];"
                         : "=r"(bh0), "=r"(bh1) : "r"(ad));
            asm("{ .reg .u64 t; cvta.to.shared.u64 t, %1; cvt.u32.u64 %0, t; }"
                : "=r"(ad) : "l"((const char*)sBl + off));
            asm volatile("ldmatrix.sync.aligned.m8n8.x2.shared.b16 {%0,%1}, [%2];"
                         : "=r"(bl0), "=r"(bl1) : "r"(ad));
#pragma unroll
            for (int mi = 0; mi < 2; mi++) {
                float* c = acc[mi][ni];
                asm volatile(
                    "mma.sync.aligned.m16n8k16.row.col.f32.bf16.bf16.f32 "
                    "{%0,%1,%2,%3}, {%4,%5,%6,%7}, {%8,%9}, {%0,%1,%2,%3};"
                    : "+f"(c[0]), "+f"(c[1]), "+f"(c[2]), "+f"(c[3])
                    : "r"(ah[mi][0]), "r"(ah[mi][1]), "r"(ah[mi][2]), "r"(ah[mi][3]),
                      "r"(bh0), "r"(bh1));
                asm volatile(
                    "mma.sync.aligned.m16n8k16.row.col.f32.bf16.bf16.f32 "
                    "{%0,%1,%2,%3}, {%4,%5,%6,%7}, {%8,%9}, {%0,%1,%2,%3};"
                    : "+f"(c[0]), "+f"(c[1]), "+f"(c[2]), "+f"(c[3])
                    : "r"(ah[mi][0]), "r"(ah[mi][1]), "r"(ah[mi][2]), "r"(ah[mi][3]),
                      "r"(bl0), "r"(bl1));
                asm volatile(
                    "mma.sync.aligned.m16n8k16.row.col.f32.bf16.bf16.f32 "
                    "{%0,%1,%2,%3}, {%4,%5,%6,%7}, {%8,%9}, {%0,%1,%2,%3};"
                    : "+f"(c[0]), "+f"(c[1]), "+f"(c[2]), "+f"(c[3])
                    : "r"(al[mi][0]), "r"(al[mi][1]), "r"(al[mi][2]), "r"(al[mi][3]),
                      "r"(bh0), "r"(bh1));
            }
        }
        __syncthreads();
    }

    // store C
#pragma unroll
    for (int mi = 0; mi < 2; mi++) {
        int r0 = bm + wm + mi * 16 + g;
        int r1 = r0 + 8;
#pragma unroll
        for (int ni = 0; ni < 8; ni++) {
            int col = bn + wn + ni * 8 + tg * 2;
            if (r0 < M)
                *(float2*)&C[(size_t)r0 * Ntot + col] = make_float2(acc[mi][ni][0], acc[mi][ni][1]);
            if (r1 < M)
                *(float2*)&C[(size_t)r1 * Ntot + col] = make_float2(acc[mi][ni][2], acc[mi][ni][3]);
        }
    }

    // fused attention projections
    const int hw = Ntot / H;                  // 64 or 128
    const int gcol0 = bn + wn;                // warp col base (multiple of 64)
    const int hh = gcol0 / hw;                // head of this warp (uniform: warp spans 64 cols)
    float pa[2][2], pd[2][2];
#pragma unroll
    for (int mi = 0; mi < 2; mi++) { pa[mi][0] = pa[mi][1] = pd[mi][0] = pd[mi][1] = 0.f; }
#pragma unroll
    for (int ni = 0; ni < 8; ni++) {
        int gc = gcol0 + ni * 8 + tg * 2;
        int ch = gc - hh * hw;
        float s0 = attS[hh * hw + ch], s1 = attS[hh * hw + ch + 1];
        float d0 = attD[hh * hw + ch], d1 = attD[hh * hw + ch + 1];
#pragma unroll
        for (int mi = 0; mi < 2; mi++) {
            pa[mi][0] += acc[mi][ni][0] * s0 + acc[mi][ni][1] * s1;
            pd[mi][0] += acc[mi][ni][0] * d0 + acc[mi][ni][1] * d1;
            pa[mi][1] += acc[mi][ni][2] * s0 + acc[mi][ni][3] * s1;
            pd[mi][1] += acc[mi][ni][2] * d0 + acc[mi][ni][3] * d1;
        }
    }
#pragma unroll
    for (int mi = 0; mi < 2; mi++)
#pragma unroll
        for (int rh = 0; rh < 2; rh++) {
            pa[mi][rh] += __shfl_xor_sync(0xffffffffu, pa[mi][rh], 1);
            pa[mi][rh] += __shfl_xor_sync(0xffffffffu, pa[mi][rh], 2);
            pd[mi][rh] += __shfl_xor_sync(0xffffffffu, pd[mi][rh], 1);
            pd[mi][rh] += __shfl_xor_sync(0xffffffffu, pd[mi][rh], 2);
        }
    if (hw == 64) {
        if (tg == 0) {
#pragma unroll
            for (int mi = 0; mi < 2; mi++)
#pragma unroll
                for (int rh = 0; rh < 2; rh++) {
                    int r = bm + wm + mi * 16 + g + rh * 8;
                    if (r < M) {
                        aS[(size_t)r * H + hh] = pa[mi][rh];
                        aD[(size_t)r * H + hh] = pd[mi][rh];
                    }
                }
        }
    } else {
        // hw == 128: combine two 64-col warp halves via smem
        int half = wid >> 2;
        if (tg == 0) {
#pragma unroll
            for (int mi = 0; mi < 2; mi++)
#pragma unroll
                for (int rh = 0; rh < 2; rh++) {
                    int r = wm + mi * 16 + g + rh * 8;
                    redA[half][r] = pa[mi][rh];
                    redD[half][r] = pd[mi][rh];
                }
        }
        __syncthreads();
        if (tid < 128) {
            int r = bm + tid;
            if (r < M) {
                aS[r] = redA[0][tid] + redA[1][tid];
                aD[r] = redD[0][tid] + redD[1][tid];
            }
        }
    }
}

// ---------------- fused one-pass segment-softmax + aggregation -------------
// layer1: block(128) per dst node; smem-staged srcs + exp terms.
__global__ void gatagg1_kernel(const float* __restrict__ b1, int N) {
    int n = blockIdx.x;
    int t = threadIdx.x;
    int h = t >> 4;
    int start = g_rowstart[n], end = g_rowstart[n + 1];
    __shared__ int ssrc[32];
    __shared__ float sex[32 * 8];
    float adst = g_adst1[n * 8 + h];
    float den = 0.f;
    float4 acc = make_float4(0.f, 0.f, 0.f, 0.f);
    for (int c0 = start; c0 < end; c0 += 32) {
        int cnt = min(32, end - c0);
        if (t < cnt) ssrc[t] = g_csrc[c0 + t];
        __syncthreads();
        // thread t computes exp for edges (t&15) and (t&15)+16 of head t>>4
        {
            int j0 = t & 15;
#pragma unroll
            for (int q = 0; q < 2; q++) {
                int j = j0 + q * 16;
                if (j < cnt) {
                    int s = ssrc[j];
                    float v = g_asrc1[s * 8 + h] + adst;
                    v = (v >= 0.f) ? v : 0.2f * v;
                    sex[j * 8 + h] = __expf(v);
                }
            }
        }
        __syncthreads();
#pragma unroll 4
        for (int j = 0; j < cnt; j++) {
            float ex = sex[j * 8 + h];
            int s = ssrc[j];
            float4 hv = *(const float4*)&g_h1[(size_t)s * 512 + t * 4];
            den += ex;
            acc.x += ex * hv.x; acc.y += ex * hv.y;
            acc.z += ex * hv.z; acc.w += ex * hv.w;
        }
        __syncthreads();
    }
    float inv = 1.f / (den + 1e-16f);
    float4 bb = *(const float4*)&b1[t * 4];
    float o[4];
    o[0] = fmaxf(fmaf(acc.x, inv, bb.x), 0.f);
    o[1] = fmaxf(fmaf(acc.y, inv, bb.y), 0.f);
    o[2] = fmaxf(fmaf(acc.z, inv, bb.z), 0.f);
    o[3] = fmaxf(fmaf(acc.w, inv, bb.w), 0.f);
    uint32_t ph[2], pl[2];
#pragma unroll
    for (int k = 0; k < 2; k++) {
        __nv_bfloat16 h0 = __float2bfloat16(o[2 * k]);
        __nv_bfloat16 h1v = __float2bfloat16(o[2 * k + 1]);
        __nv_bfloat16 l0 = __float2bfloat16(o[2 * k] - __bfloat162float(h0));
        __nv_bfloat16 l1 = __float2bfloat16(o[2 * k + 1] - __bfloat162float(h1v));
        ph[k] = (uint32_t)__bfloat16_as_ushort(h0) | ((uint32_t)__bfloat16_as_ushort(h1v) << 16);
        pl[k] = (uint32_t)__bfloat16_as_ushort(l0) | ((uint32_t)__bfloat16_as_ushort(l1) << 16);
    }
    size_t o4 = (size_t)n * 512 + t * 4;
    *(uint2*)&g_o1hi[o4] = make_uint2(ph[0], ph[1]);
    *(uint2*)&g_o1lo[o4] = make_uint2(pl[0], pl[1]);
}

// layer2 (H=1): warp per node, one pass, shfl-broadcast exp terms.
__global__ void gatagg2_kernel(const float* __restrict__ b2, int N) {
    int n = blockIdx.x * 8 + (threadIdx.x >> 5);
    if (n >= N) return;
    int lane = threadIdx.x & 31;
    int start = g_rowstart[n], end = g_rowstart[n + 1];
    float adst = g_adst2[n];
    float den = 0.f;
    float4 acc = make_float4(0.f, 0.f, 0.f, 0.f);
    for (int c0 = start; c0 < end; c0 += 32) {
        int cnt = min(32, end - c0);
        int s = 0; float ex = 0.f;
        if (lane < cnt) {
            s = g_csrc[c0 + lane];
            float v = g_asrc2[s] + adst;
            v = (v >= 0.f) ? v : 0.2f * v;
            ex = __expf(v);
        }
#pragma unroll 4
        for (int j = 0; j < cnt; j++) {
            int bs = __shfl_sync(0xffffffffu, s, j);
            float bex = __shfl_sync(0xffffffffu, ex, j);
            float4 hv = *(const float4*)&g_h2[(size_t)bs * 128 + lane * 4];
            den += bex;
            acc.x += bex * hv.x; acc.y += bex * hv.y;
            acc.z += bex * hv.z; acc.w += bex * hv.w;
        }
    }
    float inv = 1.f / (den + 1e-16f);
    float4 bb = *(const float4*)&b2[lane * 4];
    float4 o;
    o.x = fmaxf(fmaf(acc.x, inv, bb.x), 0.f);
    o.y = fmaxf(fmaf(acc.y, inv, bb.y), 0.f);
    o.z = fmaxf(fmaf(acc.z, inv, bb.z), 0.f);
    o.w = fmaxf(fmaf(acc.w, inv, bb.w), 0.f);
    *(float4*)&g_out2[(size_t)n * 128 + lane * 4] = o;
}

// ---------------- pooling + readout ----------------------------------------
__global__ void pool_kernel(const int* __restrict__ batch,
                            const float* __restrict__ wA, const float* __restrict__ bA,
                            const float* __restrict__ wM, const float* __restrict__ bM,
                            int N) {
    int n = blockIdx.x;
    int t = threadIdx.x;
    float v = g_out2[(size_t)n * 128 + t];
    __shared__ float s1[128], s2[128];
    s1[t] = v * wA[t];
    s2[t] = v * wM[t];
    __syncthreads();
    for (int off = 64; off > 0; off >>= 1) {
        if (t < off) { s1[t] += s1[t + off]; s2[t] += s2[t + off]; }
        __syncthreads();
    }
    __shared__ float wsh;
    if (t == 0) {
        float at = s1[0] + bA[0];
        float mk = 1.f / (1.f + __expf(-(s2[0] + bM[0])));
        wsh = at * mk;
    }
    __syncthreads();
    atomicAdd(&g_pooled[batch[n] * 128 + t], v * wsh);
}
__global__ void final_kernel(const float* __restrict__ Wo,
                             const float* __restrict__ bo,
                             float* __restrict__ out) {
    int i = threadIdx.x;
    int g = i >> 1, o = i & 1;
    float s = 0.f;
#pragma unroll 4
    for (int k = 0; k < 128; k++)
        s += g_pooled[g * 128 + k] * Wo[o * 128 + k];
    out[i] = s + bo[o];
}

// ---------------- launch ----------------------------------------------------
extern "C" void kernel_launch(void* const* d_in, const int* in_sizes, int n_in,
                              void* d_out, int out_size) {
    const float* x      = (const float*)d_in[0];
    const int*   ei     = (const int*)d_in[1];
    const int*   batch  = (const int*)d_in[2];
    const float* W1     = (const float*)d_in[3];
    const float* as1    = (const float*)d_in[4];
    const float* ad1    = (const float*)d_in[5];
    const float* b1     = (const float*)d_in[6];
    const float* W2     = (const float*)d_in[7];
    const float* as2    = (const float*)d_in[8];
    const float* ad2    = (const float*)d_in[9];
    const float* b2     = (const float*)d_in[10];
    const float* w_attn = (const float*)d_in[11];
    const float* b_attn = (const float*)d_in[12];
    const float* w_mask = (const float*)d_in[13];
    const float* b_mask = (const float*)d_in[14];
    const float* W_out  = (const float*)d_in[15];
    const float* b_out  = (const float*)d_in[16];
    float* out = (float*)d_out;

    int N = in_sizes[0] / 128;
    int E = in_sizes[1] / 2;
    int ET = N + E;

    float *p_h1, *p_h2, *p_as1, *p_ad1, *p_as2, *p_ad2;
    __nv_bfloat16 *p_xhi, *p_xlo, *p_o1hi, *p_o1lo, *p_w1hi, *p_w1lo, *p_w2hi, *p_w2lo;
    cudaGetSymbolAddress((void**)&p_h1, g_h1);
    cudaGetSymbolAddress((void**)&p_h2, g_h2);
    cudaGetSymbolAddress((void**)&p_as1, g_asrc1);
    cudaGetSymbolAddress((void**)&p_ad1, g_adst1);
    cudaGetSymbolAddress((void**)&p_as2, g_asrc2);
    cudaGetSymbolAddress((void**)&p_ad2, g_adst2);
    cudaGetSymbolAddress((void**)&p_xhi, g_xhi);
    cudaGetSymbolAddress((void**)&p_xlo, g_xlo);
    cudaGetSymbolAddress((void**)&p_o1hi, g_o1hi);
    cudaGetSymbolAddress((void**)&p_o1lo, g_o1lo);
    cudaGetSymbolAddress((void**)&p_w1hi, g_w1hi);
    cudaGetSymbolAddress((void**)&p_w1lo, g_w1lo);
    cudaGetSymbolAddress((void**)&p_w2hi, g_w2hi);
    cudaGetSymbolAddress((void**)&p_w2lo, g_w2lo);

    int init_n = (N > 256 * 128) ? N : 256 * 128;
    init_kernel<<<(init_n + 255) / 256, 256>>>(N);

    count_kernel<<<(ET + 255) / 256, 256>>>(ei, E, N);
    scan_kernel<<<1, 1024>>>(N, ET);
    scatter_kernel<<<(ET + 255) / 256, 256>>>(ei, E, N);

    split_kernel<<<(N * 128 + 255) / 256, 256>>>(x, p_xhi, p_xlo, N * 128);
    split_kernel<<<(512 * 128 + 255) / 256, 256>>>(W1, p_w1hi, p_w1lo, 512 * 128);
    split_kernel<<<(128 * 512 + 255) / 256, 256>>>(W2, p_w2hi, p_w2lo, 128 * 512);

    int mtiles = (N + 127) / 128;

    // layer 1: h1 = x @ W1^T, fused attn projections (H=8, hw=64)
    {
        dim3 grid(4, mtiles);
        gemm_bf16x3_kernel<<<grid, 256>>>(p_xhi, p_xlo, p_w1hi, p_w1lo, p_h1,
                                          N, 512, 128, as1, ad1, p_as1, p_ad1, 8);
    }
    gatagg1_kernel<<<N, 128>>>(b1, N);

    // layer 2: h2 = out1 @ W2^T, fused attn projections (H=1, hw=128)
    {
        dim3 grid(1, mtiles);
        gemm_bf16x3_kernel<<<grid, 256>>>(p_o1hi, p_o1lo, p_w2hi, p_w2lo, p_h2,
                                          N, 128, 512, as2, ad2, p_as2, p_ad2, 1);
    }
    gatagg2_kernel<<<(N + 7) / 8, 256>>>(b2, N);

    pool_kernel<<<N, 128>>>(batch, w_attn, b_attn, w_mask, b_mask, N);
    final_kernel<<<1, 512>>>(W_out, b_out, out);
}

// round 7
// speedup vs baseline: 1.3309x; 1.0092x over previous
#include <cuda_runtime.h>
#include <cuda_bf16.h>
#include <cstdint>

#define NMAX 20000
#define EMAX 320000
#define ETMAX (NMAX + EMAX)

// ---------------- scratch (device globals) --------------------------------
__device__ float g_h1[NMAX * 512];                 // x @ W1^T (fp32)
__device__ float g_h2[NMAX * 128];                 // out1 @ W2^T
__device__ __nv_bfloat16 g_o1hi[NMAX * 512], g_o1lo[NMAX * 512];
__device__ float g_asrc1[NMAX * 8], g_adst1[NMAX * 8];
__device__ float g_asrc2[NMAX], g_adst2[NMAX];
__device__ int g_cnt[NMAX];                        // zeroed statically; re-zeroed by scan
__device__ int g_cursor[NMAX];                     // zeroed statically; re-zeroed by gatagg1
__device__ int g_rowstart[NMAX + 1];
__device__ int g_csrc[ETMAX];
__device__ float g_pooled[256 * 128];              // zeroed statically; re-zeroed by scan

// ---------------- CSR build -------------------------------------------------
__global__ void count_kernel(const int* __restrict__ ei, int E, int N) {
    int e = blockIdx.x * blockDim.x + threadIdx.x;
    if (e >= E + N) return;
    int d = (e < E) ? ei[E + e] : (e - E);
    atomicAdd(&g_cnt[d], 1);
}
// scan also: zeroes g_cnt after consuming it, zeroes g_pooled for this run's pool.
__global__ void scan_kernel(int N, int ET) {
    __shared__ int sums[1024];
    int tid = threadIdx.x;
    for (int i = tid; i < 256 * 128; i += 1024) g_pooled[i] = 0.f;
    int CH = (N + 1023) >> 10;
    int base = tid * CH, s = 0;
    for (int j = 0; j < CH; j++) { int idx = base + j; if (idx < N) s += g_cnt[idx]; }
    sums[tid] = s;
    __syncthreads();
    for (int off = 1; off < 1024; off <<= 1) {
        int v = (tid >= off) ? sums[tid - off] : 0;
        __syncthreads();
        sums[tid] += v;
        __syncthreads();
    }
    int run = sums[tid] - s;
    for (int j = 0; j < CH; j++) {
        int idx = base + j;
        if (idx < N) {
            g_rowstart[idx] = run;
            run += g_cnt[idx];
            g_cnt[idx] = 0;                        // ready for next replay
        }
    }
    if (tid == 0) g_rowstart[N] = ET;
}
__global__ void scatter_kernel(const int* __restrict__ ei, int E, int N) {
    int e = blockIdx.x * blockDim.x + threadIdx.x;
    if (e >= E + N) return;
    int s, d;
    if (e < E) { s = ei[e]; d = ei[E + e]; }
    else       { s = d = e - E; }
    int pos = g_rowstart[d] + atomicAdd(&g_cursor[d], 1);
    g_csrc[pos] = s;
}

// ---------------- split helper ----------------------------------------------
__device__ __forceinline__ void split8(const float* g, uint4& hi, uint4& lo) {
    float4 a = *(const float4*)g;
    float4 b = *(const float4*)(g + 4);
    float v[8] = {a.x, a.y, a.z, a.w, b.x, b.y, b.z, b.w};
    uint32_t h[4], l[4];
#pragma unroll
    for (int i = 0; i < 4; i++) {
        __nv_bfloat16 h0 = __float2bfloat16(v[2 * i]);
        __nv_bfloat16 h1 = __float2bfloat16(v[2 * i + 1]);
        __nv_bfloat16 l0 = __float2bfloat16(v[2 * i] - __bfloat162float(h0));
        __nv_bfloat16 l1 = __float2bfloat16(v[2 * i + 1] - __bfloat162float(h1));
        h[i] = (uint32_t)__bfloat16_as_ushort(h0) | ((uint32_t)__bfloat16_as_ushort(h1) << 16);
        l[i] = (uint32_t)__bfloat16_as_ushort(l0) | ((uint32_t)__bfloat16_as_ushort(l1) << 16);
    }
    hi = make_uint4(h[0], h[1], h[2], h[3]);
    lo = make_uint4(l[0], l[1], l[2], l[3]);
}

// ---------------- bf16x3 HMMA GEMM + fused attn projections ----------------
// C[M,Ntot] = A @ B^T.  A: fp32 (AF32) or prepacked bf16 hi/lo.  B: fp32,
// split inline. Also emits aS[r,h], aD[r,h] (head width hw = Ntot/H).
#define TSTR 24
template <bool AF32>
__global__ void __launch_bounds__(256, 2)
gemm_kernel(const float* __restrict__ Af,
            const __nv_bfloat16* __restrict__ Ahi_g,
            const __nv_bfloat16* __restrict__ Alo_g,
            const float* __restrict__ Bf,
            float* __restrict__ C, int M, int Ntot, int K,
            const float* __restrict__ attS, const float* __restrict__ attD,
            float* __restrict__ aS, float* __restrict__ aD, int H) {
    __shared__ __nv_bfloat16 sAh[128 * TSTR], sAl[128 * TSTR];
    __shared__ __nv_bfloat16 sBh[128 * TSTR], sBl[128 * TSTR];
    __shared__ float redA[2][128], redD[2][128];

    const int tid = threadIdx.x;
    const int wid = tid >> 5, lane = tid & 31;
    const int bm = blockIdx.y * 128;
    const int bn = blockIdx.x * 128;
    const int wm = (wid & 3) * 32;
    const int wn = (wid >> 2) * 64;

    const int srow = tid >> 1;
    const int spart = tid & 1;
    const int arow = bm + srow;
    const bool avalid = arow < M;
    const int brow = bn + srow;
    const uint32_t sw = srow * TSTR + spart * 8;

    const int a_r = lane & 15;
    const int a_c = (lane >> 4) * 8;
    const int b_r = lane & 7;
    const int b_c = ((lane >> 3) & 1) * 8;

    const int g = lane >> 2;
    const int tg = lane & 3;

    float acc[2][8][4];
#pragma unroll
    for (int mi = 0; mi < 2; mi++)
#pragma unroll
        for (int ni = 0; ni < 8; ni++)
#pragma unroll
            for (int j = 0; j < 4; j++) acc[mi][ni][j] = 0.f;

    const uint4 z4 = make_uint4(0u, 0u, 0u, 0u);

    for (int k0 = 0; k0 < K; k0 += 16) {
        {
            uint4 th = z4, tl = z4;
            if (AF32) {
                if (avalid) split8(Af + (size_t)arow * K + k0 + spart * 8, th, tl);
            } else {
                const size_t ao = (size_t)arow * K + k0 + spart * 8;
                if (avalid) {
                    th = *(const uint4*)(Ahi_g + ao);
                    tl = *(const uint4*)(Alo_g + ao);
                }
            }
            *(uint4*)&sAh[sw] = th;
            *(uint4*)&sAl[sw] = tl;
            uint4 bh, bl;
            split8(Bf + (size_t)brow * K + k0 + spart * 8, bh, bl);
            *(uint4*)&sBh[sw] = bh;
            *(uint4*)&sBl[sw] = bl;
        }
        __syncthreads();

        uint32_t ah[2][4], al[2][4];
#pragma unroll
        for (int mi = 0; mi < 2; mi++) {
            uint32_t offh = (uint32_t)((wm + mi * 16 + a_r) * TSTR + a_c) * 2;
            uint32_t ad;
            asm("{ .reg .u64 t; cvta.to.shared.u64 t, %1; cvt.u32.u64 %0, t; }"
                : "=r"(ad) : "l"((const char*)sAh + offh));
            asm volatile("ldmatrix.sync.aligned.m8n8.x4.shared.b16 {%0,%1,%2,%3}, [%4];"
                         : "=r"(ah[mi][0]), "=r"(ah[mi][1]), "=r"(ah[mi][2]), "=r"(ah[mi][3])
                         : "r"(ad));
            asm("{ .reg .u64 t; cvta.to.shared.u64 t, %1; cvt.u32.u64 %0, t; }"
                : "=r"(ad) : "l"((const char*)sAl + offh));
            asm volatile("ldmatrix.sync.aligned.m8n8.x4.shared.b16 {%0,%1,%2,%3}, [%4];"
                         : "=r"(al[mi][0]), "=r"(al[mi][1]), "=r"(al[mi][2]), "=r"(al[mi][3])
                         : "r"(ad));
        }

#pragma unroll
        for (int ni = 0; ni < 8; ni++) {
            uint32_t off = (uint32_t)((wn + ni * 8 + b_r) * TSTR + b_c) * 2;
            uint32_t bh0, bh1, bl0, bl1, ad;
            asm("{ .reg .u64 t; cvta.to.shared.u64 t, %1; cvt.u32.u64 %0, t; }"
                : "=r"(ad) : "l"((const char*)sBh + off));
            asm volatile("ldmatrix.sync.aligned.m8n8.x2.shared.b16 {%0,%1}, [%2];"
                         : "=r"(bh0), "=r"(bh1) : "r"(ad));
            asm("{ .reg .u64 t; cvta.to.shared.u64 t, %1; cvt.u32.u64 %0, t; }"
                : "=r"(ad) : "l"((const char*)sBl + off));
            asm volatile("ldmatrix.sync.aligned.m8n8.x2.shared.b16 {%0,%1}, [%2];"
                         : "=r"(bl0), "=r"(bl1) : "r"(ad));
#pragma unroll
            for (int mi = 0; mi < 2; mi++) {
                float* c = acc[mi][ni];
                asm volatile(
                    "mma.sync.aligned.m16n8k16.row.col.f32.bf16.bf16.f32 "
                    "{%0,%1,%2,%3}, {%4,%5,%6,%7}, {%8,%9}, {%0,%1,%2,%3};"
                    : "+f"(c[0]), "+f"(c[1]), "+f"(c[2]), "+f"(c[3])
                    : "r"(ah[mi][0]), "r"(ah[mi][1]), "r"(ah[mi][2]), "r"(ah[mi][3]),
                      "r"(bh0), "r"(bh1));
                asm volatile(
                    "mma.sync.aligned.m16n8k16.row.col.f32.bf16.bf16.f32 "
                    "{%0,%1,%2,%3}, {%4,%5,%6,%7}, {%8,%9}, {%0,%1,%2,%3};"
                    : "+f"(c[0]), "+f"(c[1]), "+f"(c[2]), "+f"(c[3])
                    : "r"(ah[mi][0]), "r"(ah[mi][1]), "r"(ah[mi][2]), "r"(ah[mi][3]),
                      "r"(bl0), "r"(bl1));
                asm volatile(
                    "mma.sync.aligned.m16n8k16.row.col.f32.bf16.bf16.f32 "
                    "{%0,%1,%2,%3}, {%4,%5,%6,%7}, {%8,%9}, {%0,%1,%2,%3};"
                    : "+f"(c[0]), "+f"(c[1]), "+f"(c[2]), "+f"(c[3])
                    : "r"(al[mi][0]), "r"(al[mi][1]), "r"(al[mi][2]), "r"(al[mi][3]),
                      "r"(bh0), "r"(bh1));
            }
        }
        __syncthreads();
    }

    // store C
#pragma unroll
    for (int mi = 0; mi < 2; mi++) {
        int r0 = bm + wm + mi * 16 + g;
        int r1 = r0 + 8;
#pragma unroll
        for (int ni = 0; ni < 8; ni++) {
            int col = bn + wn + ni * 8 + tg * 2;
            if (r0 < M)
                *(float2*)&C[(size_t)r0 * Ntot + col] = make_float2(acc[mi][ni][0], acc[mi][ni][1]);
            if (r1 < M)
                *(float2*)&C[(size_t)r1 * Ntot + col] = make_float2(acc[mi][ni][2], acc[mi][ni][3]);
        }
    }

    // fused attention projections
    const int hw = Ntot / H;
    const int gcol0 = bn + wn;
    const int hh = gcol0 / hw;
    float pa[2][2], pd[2][2];
#pragma unroll
    for (int mi = 0; mi < 2; mi++) { pa[mi][0] = pa[mi][1] = pd[mi][0] = pd[mi][1] = 0.f; }
#pragma unroll
    for (int ni = 0; ni < 8; ni++) {
        int gc = gcol0 + ni * 8 + tg * 2;
        int ch = gc - hh * hw;
        float s0 = attS[hh * hw + ch], s1 = attS[hh * hw + ch + 1];
        float d0 = attD[hh * hw + ch], d1 = attD[hh * hw + ch + 1];
#pragma unroll
        for (int mi = 0; mi < 2; mi++) {
            pa[mi][0] += acc[mi][ni][0] * s0 + acc[mi][ni][1] * s1;
            pd[mi][0] += acc[mi][ni][0] * d0 + acc[mi][ni][1] * d1;
            pa[mi][1] += acc[mi][ni][2] * s0 + acc[mi][ni][3] * s1;
            pd[mi][1] += acc[mi][ni][2] * d0 + acc[mi][ni][3] * d1;
        }
    }
#pragma unroll
    for (int mi = 0; mi < 2; mi++)
#pragma unroll
        for (int rh = 0; rh < 2; rh++) {
            pa[mi][rh] += __shfl_xor_sync(0xffffffffu, pa[mi][rh], 1);
            pa[mi][rh] += __shfl_xor_sync(0xffffffffu, pa[mi][rh], 2);
            pd[mi][rh] += __shfl_xor_sync(0xffffffffu, pd[mi][rh], 1);
            pd[mi][rh] += __shfl_xor_sync(0xffffffffu, pd[mi][rh], 2);
        }
    if (hw == 64) {
        if (tg == 0) {
#pragma unroll
            for (int mi = 0; mi < 2; mi++)
#pragma unroll
                for (int rh = 0; rh < 2; rh++) {
                    int r = bm + wm + mi * 16 + g + rh * 8;
                    if (r < M) {
                        aS[(size_t)r * H + hh] = pa[mi][rh];
                        aD[(size_t)r * H + hh] = pd[mi][rh];
                    }
                }
        }
    } else {
        int half = wid >> 2;
        if (tg == 0) {
#pragma unroll
            for (int mi = 0; mi < 2; mi++)
#pragma unroll
                for (int rh = 0; rh < 2; rh++) {
                    int r = wm + mi * 16 + g + rh * 8;
                    redA[half][r] = pa[mi][rh];
                    redD[half][r] = pd[mi][rh];
                }
        }
        __syncthreads();
        if (tid < 128) {
            int r = bm + tid;
            if (r < M) {
                aS[r] = redA[0][tid] + redA[1][tid];
                aD[r] = redD[0][tid] + redD[1][tid];
            }
        }
    }
}

// ---------------- fused one-pass segment-softmax + aggregation -------------
__global__ void gatagg1_kernel(const float* __restrict__ b1, int N) {
    int n = blockIdx.x;
    int t = threadIdx.x;
    int h = t >> 4;
    if (t == 0) g_cursor[n] = 0;                   // reset for next replay's scatter
    int start = g_rowstart[n], end = g_rowstart[n + 1];
    __shared__ int ssrc[32];
    __shared__ float sex[32 * 8];
    float adst = g_adst1[n * 8 + h];
    float den = 0.f;
    float4 acc = make_float4(0.f, 0.f, 0.f, 0.f);
    for (int c0 = start; c0 < end; c0 += 32) {
        int cnt = min(32, end - c0);
        if (t < cnt) ssrc[t] = g_csrc[c0 + t];
        __syncthreads();
        {
            int j0 = t & 15;
#pragma unroll
            for (int q = 0; q < 2; q++) {
                int j = j0 + q * 16;
                if (j < cnt) {
                    int s = ssrc[j];
                    float v = g_asrc1[s * 8 + h] + adst;
                    v = (v >= 0.f) ? v : 0.2f * v;
                    sex[j * 8 + h] = __expf(v);
                }
            }
        }
        __syncthreads();
#pragma unroll 4
        for (int j = 0; j < cnt; j++) {
            float ex = sex[j * 8 + h];
            int s = ssrc[j];
            float4 hv = *(const float4*)&g_h1[(size_t)s * 512 + t * 4];
            den += ex;
            acc.x += ex * hv.x; acc.y += ex * hv.y;
            acc.z += ex * hv.z; acc.w += ex * hv.w;
        }
        __syncthreads();
    }
    float inv = 1.f / (den + 1e-16f);
    float4 bb = *(const float4*)&b1[t * 4];
    float o[4];
    o[0] = fmaxf(fmaf(acc.x, inv, bb.x), 0.f);
    o[1] = fmaxf(fmaf(acc.y, inv, bb.y), 0.f);
    o[2] = fmaxf(fmaf(acc.z, inv, bb.z), 0.f);
    o[3] = fmaxf(fmaf(acc.w, inv, bb.w), 0.f);
    uint32_t ph[2], pl[2];
#pragma unroll
    for (int k = 0; k < 2; k++) {
        __nv_bfloat16 h0 = __float2bfloat16(o[2 * k]);
        __nv_bfloat16 h1v = __float2bfloat16(o[2 * k + 1]);
        __nv_bfloat16 l0 = __float2bfloat16(o[2 * k] - __bfloat162float(h0));
        __nv_bfloat16 l1 = __float2bfloat16(o[2 * k + 1] - __bfloat162float(h1v));
        ph[k] = (uint32_t)__bfloat16_as_ushort(h0) | ((uint32_t)__bfloat16_as_ushort(h1v) << 16);
        pl[k] = (uint32_t)__bfloat16_as_ushort(l0) | ((uint32_t)__bfloat16_as_ushort(l1) << 16);
    }
    size_t o4 = (size_t)n * 512 + t * 4;
    *(uint2*)&g_o1hi[o4] = make_uint2(ph[0], ph[1]);
    *(uint2*)&g_o1lo[o4] = make_uint2(pl[0], pl[1]);
}

// layer2 agg + fused attention pooling (H=1): warp per node.
__global__ void gatagg2_kernel(const float* __restrict__ b2,
                               const int* __restrict__ batch,
                               const float* __restrict__ wA, const float* __restrict__ bA,
                               const float* __restrict__ wM, const float* __restrict__ bM,
                               int N) {
    int n = blockIdx.x * 8 + (threadIdx.x >> 5);
    if (n >= N) return;
    int lane = threadIdx.x & 31;
    int start = g_rowstart[n], end = g_rowstart[n + 1];
    float adst = g_adst2[n];
    float den = 0.f;
    float4 acc = make_float4(0.f, 0.f, 0.f, 0.f);
    for (int c0 = start; c0 < end; c0 += 32) {
        int cnt = min(32, end - c0);
        int s = 0; float ex = 0.f;
        if (lane < cnt) {
            s = g_csrc[c0 + lane];
            float v = g_asrc2[s] + adst;
            v = (v >= 0.f) ? v : 0.2f * v;
            ex = __expf(v);
        }
#pragma unroll 4
        for (int j = 0; j < cnt; j++) {
            int bs = __shfl_sync(0xffffffffu, s, j);
            float bex = __shfl_sync(0xffffffffu, ex, j);
            float4 hv = *(const float4*)&g_h2[(size_t)bs * 128 + lane * 4];
            den += bex;
            acc.x += bex * hv.x; acc.y += bex * hv.y;
            acc.z += bex * hv.z; acc.w += bex * hv.w;
        }
    }
    float inv = 1.f / (den + 1e-16f);
    float4 bb = *(const float4*)&b2[lane * 4];
    float4 o;
    o.x = fmaxf(fmaf(acc.x, inv, bb.x), 0.f);
    o.y = fmaxf(fmaf(acc.y, inv, bb.y), 0.f);
    o.z = fmaxf(fmaf(acc.z, inv, bb.z), 0.f);
    o.w = fmaxf(fmaf(acc.w, inv, bb.w), 0.f);

    // fused attention pooling
    float4 wAv = *(const float4*)&wA[lane * 4];
    float4 wMv = *(const float4*)&wM[lane * 4];
    float sA = o.x * wAv.x + o.y * wAv.y + o.z * wAv.z + o.w * wAv.w;
    float sM = o.x * wMv.x + o.y * wMv.y + o.z * wMv.z + o.w * wMv.w;
#pragma unroll
    for (int off = 16; off > 0; off >>= 1) {
        sA += __shfl_xor_sync(0xffffffffu, sA, off);
        sM += __shfl_xor_sync(0xffffffffu, sM, off);
    }
    float wgt = (sA + bA[0]) * (1.f / (1.f + __expf(-(sM + bM[0]))));
    float* pp = &g_pooled[batch[n] * 128 + lane * 4];
    atomicAdd(pp + 0, o.x * wgt);
    atomicAdd(pp + 1, o.y * wgt);
    atomicAdd(pp + 2, o.z * wgt);
    atomicAdd(pp + 3, o.w * wgt);
}

// ---------------- final projection ------------------------------------------
__global__ void final_kernel(const float* __restrict__ Wo,
                             const float* __restrict__ bo,
                             float* __restrict__ out) {
    int i = threadIdx.x;
    int g = i >> 1, o = i & 1;
    float s = 0.f;
#pragma unroll 4
    for (int k = 0; k < 128; k++)
        s += g_pooled[g * 128 + k] * Wo[o * 128 + k];
    out[i] = s + bo[o];
}

// ---------------- launch ----------------------------------------------------
extern "C" void kernel_launch(void* const* d_in, const int* in_sizes, int n_in,
                              void* d_out, int out_size) {
    const float* x      = (const float*)d_in[0];
    const int*   ei     = (const int*)d_in[1];
    const int*   batch  = (const int*)d_in[2];
    const float* W1     = (const float*)d_in[3];
    const float* as1    = (const float*)d_in[4];
    const float* ad1    = (const float*)d_in[5];
    const float* b1     = (const float*)d_in[6];
    const float* W2     = (const float*)d_in[7];
    const float* as2    = (const float*)d_in[8];
    const float* ad2    = (const float*)d_in[9];
    const float* b2     = (const float*)d_in[10];
    const float* w_attn = (const float*)d_in[11];
    const float* b_attn = (const float*)d_in[12];
    const float* w_mask = (const float*)d_in[13];
    const float* b_mask = (const float*)d_in[14];
    const float* W_out  = (const float*)d_in[15];
    const float* b_out  = (const float*)d_in[16];
    float* out = (float*)d_out;

    int N = in_sizes[0] / 128;
    int E = in_sizes[1] / 2;
    int ET = N + E;

    float *p_h1, *p_h2, *p_as1, *p_ad1, *p_as2, *p_ad2;
    __nv_bfloat16 *p_o1hi, *p_o1lo;
    cudaGetSymbolAddress((void**)&p_h1, g_h1);
    cudaGetSymbolAddress((void**)&p_h2, g_h2);
    cudaGetSymbolAddress((void**)&p_as1, g_asrc1);
    cudaGetSymbolAddress((void**)&p_ad1, g_adst1);
    cudaGetSymbolAddress((void**)&p_as2, g_asrc2);
    cudaGetSymbolAddress((void**)&p_ad2, g_adst2);
    cudaGetSymbolAddress((void**)&p_o1hi, g_o1hi);
    cudaGetSymbolAddress((void**)&p_o1lo, g_o1lo);

    int mtiles = (N + 127) / 128;

    count_kernel<<<(ET + 255) / 256, 256>>>(ei, E, N);
    scan_kernel<<<1, 1024>>>(N, ET);
    scatter_kernel<<<(ET + 255) / 256, 256>>>(ei, E, N);

    // layer 1: h1 = x @ W1^T (A,B fp32 split inline), fused attn (H=8)
    {
        dim3 grid(4, mtiles);
        gemm_kernel<true><<<grid, 256>>>(x, nullptr, nullptr, W1, p_h1,
                                         N, 512, 128, as1, ad1, p_as1, p_ad1, 8);
    }
    gatagg1_kernel<<<N, 128>>>(b1, N);

    // layer 2: h2 = out1 @ W2^T (A prepacked bf16, B fp32 inline), fused attn (H=1)
    {
        dim3 grid(1, mtiles);
        gemm_kernel<false><<<grid, 256>>>(nullptr, p_o1hi, p_o1lo, W2, p_h2,
                                          N, 128, 512, as2, ad2, p_as2, p_ad2, 1);
    }
    gatagg2_kernel<<<(N + 7) / 8, 256>>>(b2, batch, w_attn, b_attn, w_mask, b_mask, N);

    final_kernel<<<1, 512>>>(W_out, b_out, out);
}

// round 8
// speedup vs baseline: 1.5742x; 1.1828x over previous
#include <cuda_runtime.h>
#include <cuda_bf16.h>
#include <cstdint>

#define NMAX 20000
#define EMAX 320000
#define ETMAX (NMAX + EMAX)

// ---------------- scratch (device globals) --------------------------------
__device__ float g_h1[NMAX * 512];
__device__ float g_h2[NMAX * 128];
__device__ __nv_bfloat16 g_xhi[NMAX * 128], g_xlo[NMAX * 128];
__device__ __nv_bfloat16 g_o1hi[NMAX * 512], g_o1lo[NMAX * 512];
__device__ __nv_bfloat16 g_w1hi[512 * 128], g_w1lo[512 * 128];
__device__ __nv_bfloat16 g_w2hi[128 * 512], g_w2lo[128 * 512];
__device__ float g_asrc1[NMAX * 8], g_adst1[NMAX * 8];
__device__ float g_asrc2[NMAX], g_adst2[NMAX];
__device__ int g_cnt[NMAX];            // zero at start; scan re-zeroes after use
__device__ int g_cursor[NMAX];         // zero at start; gatagg1 re-zeroes
__device__ int g_rowstart[NMAX + 1];
__device__ int g_csrc[ETMAX];
__device__ float g_pooled[256 * 128];  // scan zeroes each run

// ---------------- small helpers --------------------------------------------
__device__ __forceinline__ uint32_t smem_u32(const void* p) {
    uint32_t a;
    asm("{ .reg .u64 t; cvta.to.shared.u64 t, %1; cvt.u32.u64 %0, t; }" : "=r"(a) : "l"(p));
    return a;
}
__device__ __forceinline__ void cpa16(uint32_t dst, const void* src, bool v) {
    int sz = v ? 16 : 0;
    asm volatile("cp.async.cg.shared.global [%0], [%1], 16, %2;" :: "r"(dst), "l"(src), "r"(sz));
}
#define CPA_COMMIT() asm volatile("cp.async.commit_group;" ::: "memory")

// ---------------- CSR build (side stream) -----------------------------------
__global__ void count_kernel(const int* __restrict__ ei, int E, int N) {
    int e = blockIdx.x * blockDim.x + threadIdx.x;
    if (e >= E + N) return;
    int d = (e < E) ? ei[E + e] : (e - E);
    atomicAdd(&g_cnt[d], 1);
}
__global__ void scan_kernel(int N, int ET) {
    __shared__ int sums[1024];
    int tid = threadIdx.x;
    for (int i = tid; i < 256 * 128; i += 1024) g_pooled[i] = 0.f;
    int CH = (N + 1023) >> 10;
    int base = tid * CH, s = 0;
    for (int j = 0; j < CH; j++) { int idx = base + j; if (idx < N) s += g_cnt[idx]; }
    sums[tid] = s;
    __syncthreads();
    for (int off = 1; off < 1024; off <<= 1) {
        int v = (tid >= off) ? sums[tid - off] : 0;
        __syncthreads();
        sums[tid] += v;
        __syncthreads();
    }
    int run = sums[tid] - s;
    for (int j = 0; j < CH; j++) {
        int idx = base + j;
        if (idx < N) { g_rowstart[idx] = run; run += g_cnt[idx]; g_cnt[idx] = 0; }
    }
    if (tid == 0) g_rowstart[N] = ET;
}
__global__ void scatter_kernel(const int* __restrict__ ei, int E, int N) {
    int e = blockIdx.x * blockDim.x + threadIdx.x;
    if (e >= E + N) return;
    int s, d;
    if (e < E) { s = ei[e]; d = ei[E + e]; }
    else       { s = d = e - E; }
    int pos = g_rowstart[d] + atomicAdd(&g_cursor[d], 1);
    g_csrc[pos] = s;
}

// ---------------- fp32 -> bf16 hi/lo split ----------------------------------
__global__ void split_kernel(const float* __restrict__ src,
                             __nv_bfloat16* __restrict__ hi,
                             __nv_bfloat16* __restrict__ lo, int n) {
    int i = blockIdx.x * blockDim.x + threadIdx.x;
    if (i >= n) return;
    float v = src[i];
    __nv_bfloat16 h = __float2bfloat16(v);
    hi[i] = h;
    lo[i] = __float2bfloat16(v - __bfloat162float(h));
}

// ---------------- pipelined bf16x3 HMMA GEMM + fused attn projections -------
// C[M,Ntot] = A @ B^T, all operands pre-split bf16 hi/lo.
// 3-stage cp.async pipeline; CTA tile 128x128; 8 warps (warp tile 32x64).
#define TSTR 24
#define TBYTES (128 * TSTR * 2)     /* 6144 per array */
#define STAGEB (4 * TBYTES)         /* 24576 per stage */
#define GEMM_SMEM (3 * STAGEB + 2048)
__global__ void __launch_bounds__(256, 2)
gemm_kernel(const __nv_bfloat16* __restrict__ Ahi, const __nv_bfloat16* __restrict__ Alo,
            const __nv_bfloat16* __restrict__ Bhi, const __nv_bfloat16* __restrict__ Blo,
            float* __restrict__ C, int M, int Ntot, int K,
            const float* __restrict__ attS, const float* __restrict__ attD,
            float* __restrict__ aS, float* __restrict__ aD, int H) {
    extern __shared__ __align__(16) char dsm[];
    const uint32_t sbase = smem_u32(dsm);
    float* redA = (float*)(dsm + 3 * STAGEB);          // [2][128]
    float* redD = (float*)(dsm + 3 * STAGEB + 1024);   // [2][128]

    const int tid = threadIdx.x;
    const int wid = tid >> 5, lane = tid & 31;
    const int bm = blockIdx.y * 128;
    const int bn = blockIdx.x * 128;
    const int wm = (wid & 3) * 32;
    const int wn = (wid >> 2) * 64;

    const int srow = tid >> 1;
    const int spart = tid & 1;
    const int arow = bm + srow;
    const bool avalid = arow < M;
    const int brow = bn + srow;
    const uint32_t swb = (uint32_t)(srow * TSTR + spart * 8) * 2;  // byte offset

    const int a_r = lane & 15;
    const int a_c = (lane >> 4) * 8;
    const int b_row = (lane & 7) + (((lane >> 4) & 1) << 3);   // n row within 16-row group
    const int b_c = ((lane >> 3) & 1) * 8;

    const int g = lane >> 2;
    const int tg = lane & 3;

    float acc[2][8][4];
#pragma unroll
    for (int mi = 0; mi < 2; mi++)
#pragma unroll
        for (int ni = 0; ni < 8; ni++)
#pragma unroll
            for (int j = 0; j < 4; j++) acc[mi][ni][j] = 0.f;

    const int nk = K >> 4;

    // pipeline issue
    auto issue = [&](int c, int st) {
        uint32_t s0 = sbase + (uint32_t)st * STAGEB + swb;
        const size_t ao = (size_t)arow * K + c * 16 + spart * 8;
        const size_t bo = (size_t)brow * K + c * 16 + spart * 8;
        cpa16(s0,              avalid ? (const void*)(Ahi + ao) : (const void*)Ahi, avalid);
        cpa16(s0 + TBYTES,     avalid ? (const void*)(Alo + ao) : (const void*)Alo, avalid);
        cpa16(s0 + 2 * TBYTES, Bhi + bo, true);
        cpa16(s0 + 3 * TBYTES, Blo + bo, true);
        CPA_COMMIT();
    };

    issue(0, 0);
    issue(1, 1);

    int cs = 0;           // compute stage
    int is = 2;           // issue stage for c+2
    for (int c = 0; c < nk; c++) {
        if (c + 2 < nk) {
            issue(c + 2, is);
            is = (is + 1 == 3) ? 0 : is + 1;
        }
        if (c + 2 < nk)      asm volatile("cp.async.wait_group 2;" ::: "memory");
        else if (c + 1 < nk) asm volatile("cp.async.wait_group 1;" ::: "memory");
        else                 asm volatile("cp.async.wait_group 0;" ::: "memory");
        __syncthreads();

        const uint32_t stb = sbase + (uint32_t)cs * STAGEB;

        uint32_t ah[2][4], al[2][4];
#pragma unroll
        for (int mi = 0; mi < 2; mi++) {
            uint32_t off = stb + (uint32_t)((wm + mi * 16 + a_r) * TSTR + a_c) * 2;
            asm volatile("ldmatrix.sync.aligned.m8n8.x4.shared.b16 {%0,%1,%2,%3}, [%4];"
                         : "=r"(ah[mi][0]), "=r"(ah[mi][1]), "=r"(ah[mi][2]), "=r"(ah[mi][3])
                         : "r"(off));
            asm volatile("ldmatrix.sync.aligned.m8n8.x4.shared.b16 {%0,%1,%2,%3}, [%4];"
                         : "=r"(al[mi][0]), "=r"(al[mi][1]), "=r"(al[mi][2]), "=r"(al[mi][3])
                         : "r"(off + TBYTES));
        }

#pragma unroll
        for (int nj = 0; nj < 4; nj++) {
            uint32_t off = stb + 2 * TBYTES +
                           (uint32_t)((wn + nj * 16 + b_row) * TSTR + b_c) * 2;
            uint32_t bh0, bh1, bh2, bh3, bl0, bl1, bl2, bl3;
            asm volatile("ldmatrix.sync.aligned.m8n8.x4.shared.b16 {%0,%1,%2,%3}, [%4];"
                         : "=r"(bh0), "=r"(bh1), "=r"(bh2), "=r"(bh3) : "r"(off));
            asm volatile("ldmatrix.sync.aligned.m8n8.x4.shared.b16 {%0,%1,%2,%3}, [%4];"
                         : "=r"(bl0), "=r"(bl1), "=r"(bl2), "=r"(bl3) : "r"(off + TBYTES));
#pragma unroll
            for (int mi = 0; mi < 2; mi++) {
                float* c0 = acc[mi][2 * nj];
                float* c1 = acc[mi][2 * nj + 1];
                asm volatile(
                    "mma.sync.aligned.m16n8k16.row.col.f32.bf16.bf16.f32 "
                    "{%0,%1,%2,%3}, {%4,%5,%6,%7}, {%8,%9}, {%0,%1,%2,%3};"
                    : "+f"(c0[0]), "+f"(c0[1]), "+f"(c0[2]), "+f"(c0[3])
                    : "r"(ah[mi][0]), "r"(ah[mi][1]), "r"(ah[mi][2]), "r"(ah[mi][3]),
                      "r"(bh0), "r"(bh1));
                asm volatile(
                    "mma.sync.aligned.m16n8k16.row.col.f32.bf16.bf16.f32 "
                    "{%0,%1,%2,%3}, {%4,%5,%6,%7}, {%8,%9}, {%0,%1,%2,%3};"
                    : "+f"(c0[0]), "+f"(c0[1]), "+f"(c0[2]), "+f"(c0[3])
                    : "r"(ah[mi][0]), "r"(ah[mi][1]), "r"(ah[mi][2]), "r"(ah[mi][3]),
                      "r"(bl0), "r"(bl1));
                asm volatile(
                    "mma.sync.aligned.m16n8k16.row.col.f32.bf16.bf16.f32 "
                    "{%0,%1,%2,%3}, {%4,%5,%6,%7}, {%8,%9}, {%0,%1,%2,%3};"
                    : "+f"(c0[0]), "+f"(c0[1]), "+f"(c0[2]), "+f"(c0[3])
                    : "r"(al[mi][0]), "r"(al[mi][1]), "r"(al[mi][2]), "r"(al[mi][3]),
                      "r"(bh0), "r"(bh1));
                asm volatile(
                    "mma.sync.aligned.m16n8k16.row.col.f32.bf16.bf16.f32 "
                    "{%0,%1,%2,%3}, {%4,%5,%6,%7}, {%8,%9}, {%0,%1,%2,%3};"
                    : "+f"(c1[0]), "+f"(c1[1]), "+f"(c1[2]), "+f"(c1[3])
                    : "r"(ah[mi][0]), "r"(ah[mi][1]), "r"(ah[mi][2]), "r"(ah[mi][3]),
                      "r"(bh2), "r"(bh3));
                asm volatile(
                    "mma.sync.aligned.m16n8k16.row.col.f32.bf16.bf16.f32 "
                    "{%0,%1,%2,%3}, {%4,%5,%6,%7}, {%8,%9}, {%0,%1,%2,%3};"
                    : "+f"(c1[0]), "+f"(c1[1]), "+f"(c1[2]), "+f"(c1[3])
                    : "r"(ah[mi][0]), "r"(ah[mi][1]), "r"(ah[mi][2]), "r"(ah[mi][3]),
                      "r"(bl2), "r"(bl3));
                asm volatile(
                    "mma.sync.aligned.m16n8k16.row.col.f32.bf16.bf16.f32 "
                    "{%0,%1,%2,%3}, {%4,%5,%6,%7}, {%8,%9}, {%0,%1,%2,%3};"
                    : "+f"(c1[0]), "+f"(c1[1]), "+f"(c1[2]), "+f"(c1[3])
                    : "r"(al[mi][0]), "r"(al[mi][1]), "r"(al[mi][2]), "r"(al[mi][3]),
                      "r"(bh2), "r"(bh3));
            }
        }
        __syncthreads();
        cs = (cs + 1 == 3) ? 0 : cs + 1;
    }

    // store C
#pragma unroll
    for (int mi = 0; mi < 2; mi++) {
        int r0 = bm + wm + mi * 16 + g;
        int r1 = r0 + 8;
#pragma unroll
        for (int ni = 0; ni < 8; ni++) {
            int col = bn + wn + ni * 8 + tg * 2;
            if (r0 < M)
                *(float2*)&C[(size_t)r0 * Ntot + col] = make_float2(acc[mi][ni][0], acc[mi][ni][1]);
            if (r1 < M)
                *(float2*)&C[(size_t)r1 * Ntot + col] = make_float2(acc[mi][ni][2], acc[mi][ni][3]);
        }
    }

    // fused attention projections
    const int hw = Ntot / H;
    const int gcol0 = bn + wn;
    const int hh = gcol0 / hw;
    float pa[2][2], pd[2][2];
#pragma unroll
    for (int mi = 0; mi < 2; mi++) { pa[mi][0] = pa[mi][1] = pd[mi][0] = pd[mi][1] = 0.f; }
#pragma unroll
    for (int ni = 0; ni < 8; ni++) {
        int gc = gcol0 + ni * 8 + tg * 2;
        int ch = gc - hh * hw;
        float s0 = attS[hh * hw + ch], s1 = attS[hh * hw + ch + 1];
        float d0 = attD[hh * hw + ch], d1 = attD[hh * hw + ch + 1];
#pragma unroll
        for (int mi = 0; mi < 2; mi++) {
            pa[mi][0] += acc[mi][ni][0] * s0 + acc[mi][ni][1] * s1;
            pd[mi][0] += acc[mi][ni][0] * d0 + acc[mi][ni][1] * d1;
            pa[mi][1] += acc[mi][ni][2] * s0 + acc[mi][ni][3] * s1;
            pd[mi][1] += acc[mi][ni][2] * d0 + acc[mi][ni][3] * d1;
        }
    }
#pragma unroll
    for (int mi = 0; mi < 2; mi++)
#pragma unroll
        for (int rh = 0; rh < 2; rh++) {
            pa[mi][rh] += __shfl_xor_sync(0xffffffffu, pa[mi][rh], 1);
            pa[mi][rh] += __shfl_xor_sync(0xffffffffu, pa[mi][rh], 2);
            pd[mi][rh] += __shfl_xor_sync(0xffffffffu, pd[mi][rh], 1);
            pd[mi][rh] += __shfl_xor_sync(0xffffffffu, pd[mi][rh], 2);
        }
    if (hw == 64) {
        if (tg == 0) {
#pragma unroll
            for (int mi = 0; mi < 2; mi++)
#pragma unroll
                for (int rh = 0; rh < 2; rh++) {
                    int r = bm + wm + mi * 16 + g + rh * 8;
                    if (r < M) {
                        aS[(size_t)r * H + hh] = pa[mi][rh];
                        aD[(size_t)r * H + hh] = pd[mi][rh];
                    }
                }
        }
    } else {
        int half = wid >> 2;
        if (tg == 0) {
#pragma unroll
            for (int mi = 0; mi < 2; mi++)
#pragma unroll
                for (int rh = 0; rh < 2; rh++) {
                    int r = wm + mi * 16 + g + rh * 8;
                    redA[half * 128 + r] = pa[mi][rh];
                    redD[half * 128 + r] = pd[mi][rh];
                }
        }
        __syncthreads();
        if (tid < 128) {
            int r = bm + tid;
            if (r < M) {
                aS[r] = redA[tid] + redA[128 + tid];
                aD[r] = redD[tid] + redD[128 + tid];
            }
        }
    }
}

// ---------------- fused one-pass segment-softmax + aggregation -------------
__global__ void gatagg1_kernel(const float* __restrict__ b1, int N) {
    int n = blockIdx.x;
    int t = threadIdx.x;
    int h = t >> 4;
    if (t == 0) g_cursor[n] = 0;
    int start = g_rowstart[n], end = g_rowstart[n + 1];
    __shared__ int ssrc[32];
    __shared__ float sex[32 * 8];
    float adst = g_adst1[n * 8 + h];
    float den = 0.f;
    float4 acc = make_float4(0.f, 0.f, 0.f, 0.f);
    for (int c0 = start; c0 < end; c0 += 32) {
        int cnt = min(32, end - c0);
        if (t < cnt) ssrc[t] = g_csrc[c0 + t];
        __syncthreads();
        {
            int j0 = t & 15;
#pragma unroll
            for (int q = 0; q < 2; q++) {
                int j = j0 + q * 16;
                if (j < cnt) {
                    int s = ssrc[j];
                    float v = g_asrc1[s * 8 + h] + adst;
                    v = (v >= 0.f) ? v : 0.2f * v;
                    sex[j * 8 + h] = __expf(v);
                }
            }
        }
        __syncthreads();
#pragma unroll 4
        for (int j = 0; j < cnt; j++) {
            float ex = sex[j * 8 + h];
            int s = ssrc[j];
            float4 hv = *(const float4*)&g_h1[(size_t)s * 512 + t * 4];
            den += ex;
            acc.x += ex * hv.x; acc.y += ex * hv.y;
            acc.z += ex * hv.z; acc.w += ex * hv.w;
        }
        __syncthreads();
    }
    float inv = 1.f / (den + 1e-16f);
    float4 bb = *(const float4*)&b1[t * 4];
    float o[4];
    o[0] = fmaxf(fmaf(acc.x, inv, bb.x), 0.f);
    o[1] = fmaxf(fmaf(acc.y, inv, bb.y), 0.f);
    o[2] = fmaxf(fmaf(acc.z, inv, bb.z), 0.f);
    o[3] = fmaxf(fmaf(acc.w, inv, bb.w), 0.f);
    uint32_t ph[2], pl[2];
#pragma unroll
    for (int k = 0; k < 2; k++) {
        __nv_bfloat16 h0 = __float2bfloat16(o[2 * k]);
        __nv_bfloat16 h1v = __float2bfloat16(o[2 * k + 1]);
        __nv_bfloat16 l0 = __float2bfloat16(o[2 * k] - __bfloat162float(h0));
        __nv_bfloat16 l1 = __float2bfloat16(o[2 * k + 1] - __bfloat162float(h1v));
        ph[k] = (uint32_t)__bfloat16_as_ushort(h0) | ((uint32_t)__bfloat16_as_ushort(h1v) << 16);
        pl[k] = (uint32_t)__bfloat16_as_ushort(l0) | ((uint32_t)__bfloat16_as_ushort(l1) << 16);
    }
    size_t o4 = (size_t)n * 512 + t * 4;
    *(uint2*)&g_o1hi[o4] = make_uint2(ph[0], ph[1]);
    *(uint2*)&g_o1lo[o4] = make_uint2(pl[0], pl[1]);
}

// layer2 agg + fused attention pooling (H=1): warp per node.
__global__ void gatagg2_kernel(const float* __restrict__ b2,
                               const int* __restrict__ batch,
                               const float* __restrict__ wA, const float* __restrict__ bA,
                               const float* __restrict__ wM, const float* __restrict__ bM,
                               int N) {
    int n = blockIdx.x * 8 + (threadIdx.x >> 5);
    if (n >= N) return;
    int lane = threadIdx.x & 31;
    int start = g_rowstart[n], end = g_rowstart[n + 1];
    float adst = g_adst2[n];
    float den = 0.f;
    float4 acc = make_float4(0.f, 0.f, 0.f, 0.f);
    for (int c0 = start; c0 < end; c0 += 32) {
        int cnt = min(32, end - c0);
        int s = 0; float ex = 0.f;
        if (lane < cnt) {
            s = g_csrc[c0 + lane];
            float v = g_asrc2[s] + adst;
            v = (v >= 0.f) ? v : 0.2f * v;
            ex = __expf(v);
        }
#pragma unroll 4
        for (int j = 0; j < cnt; j++) {
            int bs = __shfl_sync(0xffffffffu, s, j);
            float bex = __shfl_sync(0xffffffffu, ex, j);
            float4 hv = *(const float4*)&g_h2[(size_t)bs * 128 + lane * 4];
            den += bex;
            acc.x += bex * hv.x; acc.y += bex * hv.y;
            acc.z += bex * hv.z; acc.w += bex * hv.w;
        }
    }
    float inv = 1.f / (den + 1e-16f);
    float4 bb = *(const float4*)&b2[lane * 4];
    float4 o;
    o.x = fmaxf(fmaf(acc.x, inv, bb.x), 0.f);
    o.y = fmaxf(fmaf(acc.y, inv, bb.y), 0.f);
    o.z = fmaxf(fmaf(acc.z, inv, bb.z), 0.f);
    o.w = fmaxf(fmaf(acc.w, inv, bb.w), 0.f);

    float4 wAv = *(const float4*)&wA[lane * 4];
    float4 wMv = *(const float4*)&wM[lane * 4];
    float sA = o.x * wAv.x + o.y * wAv.y + o.z * wAv.z + o.w * wAv.w;
    float sM = o.x * wMv.x + o.y * wMv.y + o.z * wMv.z + o.w * wMv.w;
#pragma unroll
    for (int off = 16; off > 0; off >>= 1) {
        sA += __shfl_xor_sync(0xffffffffu, sA, off);
        sM += __shfl_xor_sync(0xffffffffu, sM, off);
    }
    float wgt = (sA + bA[0]) * (1.f / (1.f + __expf(-(sM + bM[0]))));
    float* pp = &g_pooled[batch[n] * 128 + lane * 4];
    atomicAdd(pp + 0, o.x * wgt);
    atomicAdd(pp + 1, o.y * wgt);
    atomicAdd(pp + 2, o.z * wgt);
    atomicAdd(pp + 3, o.w * wgt);
}

// ---------------- final projection ------------------------------------------
__global__ void final_kernel(const float* __restrict__ Wo,
                             const float* __restrict__ bo,
                             float* __restrict__ out) {
    int i = threadIdx.x;
    int g = i >> 1, o = i & 1;
    float s = 0.f;
#pragma unroll 4
    for (int k = 0; k < 128; k++)
        s += g_pooled[g * 128 + k] * Wo[o * 128 + k];
    out[i] = s + bo[o];
}

// ---------------- launch ----------------------------------------------------
extern "C" void kernel_launch(void* const* d_in, const int* in_sizes, int n_in,
                              void* d_out, int out_size) {
    const float* x      = (const float*)d_in[0];
    const int*   ei     = (const int*)d_in[1];
    const int*   batch  = (const int*)d_in[2];
    const float* W1     = (const float*)d_in[3];
    const float* as1    = (const float*)d_in[4];
    const float* ad1    = (const float*)d_in[5];
    const float* b1     = (const float*)d_in[6];
    const float* W2     = (const float*)d_in[7];
    const float* as2    = (const float*)d_in[8];
    const float* ad2    = (const float*)d_in[9];
    const float* b2     = (const float*)d_in[10];
    const float* w_attn = (const float*)d_in[11];
    const float* b_attn = (const float*)d_in[12];
    const float* w_mask = (const float*)d_in[13];
    const float* b_mask = (const float*)d_in[14];
    const float* W_out  = (const float*)d_in[15];
    const float* b_out  = (const float*)d_in[16];
    float* out = (float*)d_out;

    int N = in_sizes[0] / 128;
    int E = in_sizes[1] / 2;
    int ET = N + E;

    float *p_h1, *p_h2, *p_as1, *p_ad1, *p_as2, *p_ad2;
    __nv_bfloat16 *p_xhi, *p_xlo, *p_o1hi, *p_o1lo, *p_w1hi, *p_w1lo, *p_w2hi, *p_w2lo;
    cudaGetSymbolAddress((void**)&p_h1, g_h1);
    cudaGetSymbolAddress((void**)&p_h2, g_h2);
    cudaGetSymbolAddress((void**)&p_as1, g_asrc1);
    cudaGetSymbolAddress((void**)&p_ad1, g_adst1);
    cudaGetSymbolAddress((void**)&p_as2, g_asrc2);
    cudaGetSymbolAddress((void**)&p_ad2, g_adst2);
    cudaGetSymbolAddress((void**)&p_xhi, g_xhi);
    cudaGetSymbolAddress((void**)&p_xlo, g_xlo);
    cudaGetSymbolAddress((void**)&p_o1hi, g_o1hi);
    cudaGetSymbolAddress((void**)&p_o1lo, g_o1lo);
    cudaGetSymbolAddress((void**)&p_w1hi, g_w1hi);
    cudaGetSymbolAddress((void**)&p_w1lo, g_w1lo);
    cudaGetSymbolAddress((void**)&p_w2hi, g_w2hi);
    cudaGetSymbolAddress((void**)&p_w2lo, g_w2lo);

    cudaFuncSetAttribute(gemm_kernel, cudaFuncAttributeMaxDynamicSharedMemorySize, GEMM_SMEM);

    // one-time side stream + events (created on the uncaptured correctness call)
    static cudaStream_t s_side = nullptr;
    static cudaEvent_t s_evF = nullptr, s_evJ = nullptr;
    if (s_side == nullptr) {
        cudaStreamCreateWithFlags(&s_side, cudaStreamNonBlocking);
        cudaEventCreateWithFlags(&s_evF, cudaEventDisableTiming);
        cudaEventCreateWithFlags(&s_evJ, cudaEventDisableTiming);
    }

    int mtiles = (N + 127) / 128;

    // ---- fork: CSR build on side stream ----
    cudaEventRecord(s_evF, 0);
    cudaStreamWaitEvent(s_side, s_evF, 0);
    count_kernel<<<(ET + 255) / 256, 256, 0, s_side>>>(ei, E, N);
    scan_kernel<<<1, 1024, 0, s_side>>>(N, ET);
    scatter_kernel<<<(ET + 255) / 256, 256, 0, s_side>>>(ei, E, N);
    cudaEventRecord(s_evJ, s_side);

    // ---- main stream: splits + gemm1 (independent of CSR) ----
    split_kernel<<<(N * 128 + 255) / 256, 256>>>(x, p_xhi, p_xlo, N * 128);
    split_kernel<<<(512 * 128 + 255) / 256, 256>>>(W1, p_w1hi, p_w1lo, 512 * 128);
    split_kernel<<<(128 * 512 + 255) / 256, 256>>>(W2, p_w2hi, p_w2lo, 128 * 512);

    {
        dim3 grid(4, mtiles);
        gemm_kernel<<<grid, 256, GEMM_SMEM>>>(p_xhi, p_xlo, p_w1hi, p_w1lo, p_h1,
                                              N, 512, 128, as1, ad1, p_as1, p_ad1, 8);
    }

    // ---- join CSR before the gather ----
    cudaStreamWaitEvent(0, s_evJ, 0);

    gatagg1_kernel<<<N, 128>>>(b1, N);

    {
        dim3 grid(1, mtiles);
        gemm_kernel<<<grid, 256, GEMM_SMEM>>>(p_o1hi, p_o1lo, p_w2hi, p_w2lo, p_h2,
                                              N, 128, 512, as2, ad2, p_as2, p_ad2, 1);
    }
    gatagg2_kernel<<<(N + 7) / 8, 256>>>(b2, batch, w_attn, b_attn, w_mask, b_mask, N);

    final_kernel<<<1, 512>>>(W_out, b_out, out);
}

// round 9
// speedup vs baseline: 1.7747x; 1.1274x over previous
#include <cuda_runtime.h>
#include <cuda_bf16.h>
#include <cuda_fp16.h>
#include <cstdint>

#define NMAX 20000
#define EMAX 320000
#define ETMAX (NMAX + EMAX)

// ---------------- scratch (device globals) --------------------------------
__device__ __half g_h1h[NMAX * 512];               // x @ W1^T (fp16)
__device__ __half g_h2h[NMAX * 128];               // out1 @ W2^T (fp16)
__device__ __nv_bfloat16 g_xhi[NMAX * 128], g_xlo[NMAX * 128];
__device__ __nv_bfloat16 g_o1hi[NMAX * 512], g_o1lo[NMAX * 512];
__device__ __nv_bfloat16 g_w1hi[512 * 128], g_w1lo[512 * 128];
__device__ __nv_bfloat16 g_w2hi[128 * 512], g_w2lo[128 * 512];
__device__ float g_asrc1[NMAX * 8], g_adst1[NMAX * 8];
__device__ float g_asrc2[NMAX], g_adst2[NMAX];
__device__ int g_cnt[NMAX];            // zero at start; scan re-zeroes after use
__device__ int g_cursor[NMAX];         // zero at start; gatagg1 re-zeroes
__device__ int g_rowstart[NMAX + 1];
__device__ int g_csrc[ETMAX];
__device__ float g_pooled[256 * 128];  // scan zeroes each run

// ---------------- small helpers --------------------------------------------
__device__ __forceinline__ uint32_t smem_u32(const void* p) {
    uint32_t a;
    asm("{ .reg .u64 t; cvta.to.shared.u64 t, %1; cvt.u32.u64 %0, t; }" : "=r"(a) : "l"(p));
    return a;
}
__device__ __forceinline__ void cpa16(uint32_t dst, const void* src, bool v) {
    int sz = v ? 16 : 0;
    asm volatile("cp.async.cg.shared.global [%0], [%1], 16, %2;" :: "r"(dst), "l"(src), "r"(sz));
}
#define CPA_COMMIT() asm volatile("cp.async.commit_group;" ::: "memory")

// ---------------- CSR build (side stream) -----------------------------------
__global__ void count_kernel(const int* __restrict__ ei, int E, int N) {
    int e = blockIdx.x * blockDim.x + threadIdx.x;
    if (e >= E + N) return;
    int d = (e < E) ? ei[E + e] : (e - E);
    atomicAdd(&g_cnt[d], 1);
}
__global__ void scan_kernel(int N, int ET) {
    __shared__ int sums[1024];
    int tid = threadIdx.x;
    for (int i = tid; i < 256 * 128; i += 1024) g_pooled[i] = 0.f;
    int CH = (N + 1023) >> 10;
    int base = tid * CH, s = 0;
    for (int j = 0; j < CH; j++) { int idx = base + j; if (idx < N) s += g_cnt[idx]; }
    sums[tid] = s;
    __syncthreads();
    for (int off = 1; off < 1024; off <<= 1) {
        int v = (tid >= off) ? sums[tid - off] : 0;
        __syncthreads();
        sums[tid] += v;
        __syncthreads();
    }
    int run = sums[tid] - s;
    for (int j = 0; j < CH; j++) {
        int idx = base + j;
        if (idx < N) { g_rowstart[idx] = run; run += g_cnt[idx]; g_cnt[idx] = 0; }
    }
    if (tid == 0) g_rowstart[N] = ET;
}
__global__ void scatter_kernel(const int* __restrict__ ei, int E, int N) {
    int e = blockIdx.x * blockDim.x + threadIdx.x;
    if (e >= E + N) return;
    int s, d;
    if (e < E) { s = ei[e]; d = ei[E + e]; }
    else       { s = d = e - E; }
    int pos = g_rowstart[d] + atomicAdd(&g_cursor[d], 1);
    g_csrc[pos] = s;
}

// ---------------- merged vectorized fp32 -> bf16 hi/lo split -----------------
// one launch: x (n0), W1 (n1), W2 (n2); 8 elements per thread.
__global__ void split3_kernel(const float* __restrict__ x,
                              __nv_bfloat16* __restrict__ xhi, __nv_bfloat16* __restrict__ xlo,
                              int n0,
                              const float* __restrict__ w1,
                              __nv_bfloat16* __restrict__ w1hi, __nv_bfloat16* __restrict__ w1lo,
                              int n1,
                              const float* __restrict__ w2,
                              __nv_bfloat16* __restrict__ w2hi, __nv_bfloat16* __restrict__ w2lo,
                              int n2) {
    int i8 = (blockIdx.x * blockDim.x + threadIdx.x) * 8;
    const float* src;
    __nv_bfloat16 *hi, *lo;
    int off;
    if (i8 < n0) { src = x; hi = xhi; lo = xlo; off = i8; }
    else if (i8 < n0 + n1) { src = w1; hi = w1hi; lo = w1lo; off = i8 - n0; }
    else if (i8 < n0 + n1 + n2) { src = w2; hi = w2hi; lo = w2lo; off = i8 - n0 - n1; }
    else return;
    float4 a = *(const float4*)(src + off);
    float4 b = *(const float4*)(src + off + 4);
    float v[8] = {a.x, a.y, a.z, a.w, b.x, b.y, b.z, b.w};
    uint32_t hp[4], lp[4];
#pragma unroll
    for (int i = 0; i < 4; i++) {
        __nv_bfloat16 h0 = __float2bfloat16(v[2 * i]);
        __nv_bfloat16 h1 = __float2bfloat16(v[2 * i + 1]);
        __nv_bfloat16 l0 = __float2bfloat16(v[2 * i] - __bfloat162float(h0));
        __nv_bfloat16 l1 = __float2bfloat16(v[2 * i + 1] - __bfloat162float(h1));
        hp[i] = (uint32_t)__bfloat16_as_ushort(h0) | ((uint32_t)__bfloat16_as_ushort(h1) << 16);
        lp[i] = (uint32_t)__bfloat16_as_ushort(l0) | ((uint32_t)__bfloat16_as_ushort(l1) << 16);
    }
    *(uint4*)(hi + off) = make_uint4(hp[0], hp[1], hp[2], hp[3]);
    *(uint4*)(lo + off) = make_uint4(lp[0], lp[1], lp[2], lp[3]);
}

// ---------------- pipelined bf16x3 HMMA GEMM + fused attn projections -------
// C[M,Ntot] (fp16) = A @ B^T, operands pre-split bf16 hi/lo. 3-stage cp.async.
#define TSTR 24
#define TBYTES (128 * TSTR * 2)
#define STAGEB (4 * TBYTES)
#define GEMM_SMEM (3 * STAGEB + 2048)
__global__ void __launch_bounds__(256, 2)
gemm_kernel(const __nv_bfloat16* __restrict__ Ahi, const __nv_bfloat16* __restrict__ Alo,
            const __nv_bfloat16* __restrict__ Bhi, const __nv_bfloat16* __restrict__ Blo,
            __half* __restrict__ C, int M, int Ntot, int K,
            const float* __restrict__ attS, const float* __restrict__ attD,
            float* __restrict__ aS, float* __restrict__ aD, int H) {
    extern __shared__ __align__(16) char dsm[];
    const uint32_t sbase = smem_u32(dsm);
    float* redA = (float*)(dsm + 3 * STAGEB);
    float* redD = (float*)(dsm + 3 * STAGEB + 1024);

    const int tid = threadIdx.x;
    const int wid = tid >> 5, lane = tid & 31;
    const int bm = blockIdx.y * 128;
    const int bn = blockIdx.x * 128;
    const int wm = (wid & 3) * 32;
    const int wn = (wid >> 2) * 64;

    const int srow = tid >> 1;
    const int spart = tid & 1;
    const int arow = bm + srow;
    const bool avalid = arow < M;
    const int brow = bn + srow;
    const uint32_t swb = (uint32_t)(srow * TSTR + spart * 8) * 2;

    const int a_r = lane & 15;
    const int a_c = (lane >> 4) * 8;
    const int b_row = (lane & 7) + (((lane >> 4) & 1) << 3);
    const int b_c = ((lane >> 3) & 1) * 8;

    const int g = lane >> 2;
    const int tg = lane & 3;

    float acc[2][8][4];
#pragma unroll
    for (int mi = 0; mi < 2; mi++)
#pragma unroll
        for (int ni = 0; ni < 8; ni++)
#pragma unroll
            for (int j = 0; j < 4; j++) acc[mi][ni][j] = 0.f;

    const int nk = K >> 4;

    auto issue = [&](int c, int st) {
        uint32_t s0 = sbase + (uint32_t)st * STAGEB + swb;
        const size_t ao = (size_t)arow * K + c * 16 + spart * 8;
        const size_t bo = (size_t)brow * K + c * 16 + spart * 8;
        cpa16(s0,              avalid ? (const void*)(Ahi + ao) : (const void*)Ahi, avalid);
        cpa16(s0 + TBYTES,     avalid ? (const void*)(Alo + ao) : (const void*)Alo, avalid);
        cpa16(s0 + 2 * TBYTES, Bhi + bo, true);
        cpa16(s0 + 3 * TBYTES, Blo + bo, true);
        CPA_COMMIT();
    };

    issue(0, 0);
    issue(1, 1);

    int cs = 0;
    int is = 2;
    for (int c = 0; c < nk; c++) {
        if (c + 2 < nk) {
            issue(c + 2, is);
            is = (is + 1 == 3) ? 0 : is + 1;
        }
        if (c + 2 < nk)      asm volatile("cp.async.wait_group 2;" ::: "memory");
        else if (c + 1 < nk) asm volatile("cp.async.wait_group 1;" ::: "memory");
        else                 asm volatile("cp.async.wait_group 0;" ::: "memory");
        __syncthreads();

        const uint32_t stb = sbase + (uint32_t)cs * STAGEB;

        uint32_t ah[2][4], al[2][4];
#pragma unroll
        for (int mi = 0; mi < 2; mi++) {
            uint32_t off = stb + (uint32_t)((wm + mi * 16 + a_r) * TSTR + a_c) * 2;
            asm volatile("ldmatrix.sync.aligned.m8n8.x4.shared.b16 {%0,%1,%2,%3}, [%4];"
                         : "=r"(ah[mi][0]), "=r"(ah[mi][1]), "=r"(ah[mi][2]), "=r"(ah[mi][3])
                         : "r"(off));
            asm volatile("ldmatrix.sync.aligned.m8n8.x4.shared.b16 {%0,%1,%2,%3}, [%4];"
                         : "=r"(al[mi][0]), "=r"(al[mi][1]), "=r"(al[mi][2]), "=r"(al[mi][3])
                         : "r"(off + TBYTES));
        }

#pragma unroll
        for (int nj = 0; nj < 4; nj++) {
            uint32_t off = stb + 2 * TBYTES +
                           (uint32_t)((wn + nj * 16 + b_row) * TSTR + b_c) * 2;
            uint32_t bh0, bh1, bh2, bh3, bl0, bl1, bl2, bl3;
            asm volatile("ldmatrix.sync.aligned.m8n8.x4.shared.b16 {%0,%1,%2,%3}, [%4];"
                         : "=r"(bh0), "=r"(bh1), "=r"(bh2), "=r"(bh3) : "r"(off));
            asm volatile("ldmatrix.sync.aligned.m8n8.x4.shared.b16 {%0,%1,%2,%3}, [%4];"
                         : "=r"(bl0), "=r"(bl1), "=r"(bl2), "=r"(bl3) : "r"(off + TBYTES));
#pragma unroll
            for (int mi = 0; mi < 2; mi++) {
                float* c0 = acc[mi][2 * nj];
                float* c1 = acc[mi][2 * nj + 1];
                asm volatile(
                    "mma.sync.aligned.m16n8k16.row.col.f32.bf16.bf16.f32 "
                    "{%0,%1,%2,%3}, {%4,%5,%6,%7}, {%8,%9}, {%0,%1,%2,%3};"
                    : "+f"(c0[0]), "+f"(c0[1]), "+f"(c0[2]), "+f"(c0[3])
                    : "r"(ah[mi][0]), "r"(ah[mi][1]), "r"(ah[mi][2]), "r"(ah[mi][3]),
                      "r"(bh0), "r"(bh1));
                asm volatile(
                    "mma.sync.aligned.m16n8k16.row.col.f32.bf16.bf16.f32 "
                    "{%0,%1,%2,%3}, {%4,%5,%6,%7}, {%8,%9}, {%0,%1,%2,%3};"
                    : "+f"(c0[0]), "+f"(c0[1]), "+f"(c0[2]), "+f"(c0[3])
                    : "r"(ah[mi][0]), "r"(ah[mi][1]), "r"(ah[mi][2]), "r"(ah[mi][3]),
                      "r"(bl0), "r"(bl1));
                asm volatile(
                    "mma.sync.aligned.m16n8k16.row.col.f32.bf16.bf16.f32 "
                    "{%0,%1,%2,%3}, {%4,%5,%6,%7}, {%8,%9}, {%0,%1,%2,%3};"
                    : "+f"(c0[0]), "+f"(c0[1]), "+f"(c0[2]), "+f"(c0[3])
                    : "r"(al[mi][0]), "r"(al[mi][1]), "r"(al[mi][2]), "r"(al[mi][3]),
                      "r"(bh0), "r"(bh1));
                asm volatile(
                    "mma.sync.aligned.m16n8k16.row.col.f32.bf16.bf16.f32 "
                    "{%0,%1,%2,%3}, {%4,%5,%6,%7}, {%8,%9}, {%0,%1,%2,%3};"
                    : "+f"(c1[0]), "+f"(c1[1]), "+f"(c1[2]), "+f"(c1[3])
                    : "r"(ah[mi][0]), "r"(ah[mi][1]), "r"(ah[mi][2]), "r"(ah[mi][3]),
                      "r"(bh2), "r"(bh3));
                asm volatile(
                    "mma.sync.aligned.m16n8k16.row.col.f32.bf16.bf16.f32 "
                    "{%0,%1,%2,%3}, {%4,%5,%6,%7}, {%8,%9}, {%0,%1,%2,%3};"
                    : "+f"(c1[0]), "+f"(c1[1]), "+f"(c1[2]), "+f"(c1[3])
                    : "r"(ah[mi][0]), "r"(ah[mi][1]), "r"(ah[mi][2]), "r"(ah[mi][3]),
                      "r"(bl2), "r"(bl3));
                asm volatile(
                    "mma.sync.aligned.m16n8k16.row.col.f32.bf16.bf16.f32 "
                    "{%0,%1,%2,%3}, {%4,%5,%6,%7}, {%8,%9}, {%0,%1,%2,%3};"
                    : "+f"(c1[0]), "+f"(c1[1]), "+f"(c1[2]), "+f"(c1[3])
                    : "r"(al[mi][0]), "r"(al[mi][1]), "r"(al[mi][2]), "r"(al[mi][3]),
                      "r"(bh2), "r"(bh3));
            }
        }
        __syncthreads();
        cs = (cs + 1 == 3) ? 0 : cs + 1;
    }

    // store C (fp16)
#pragma unroll
    for (int mi = 0; mi < 2; mi++) {
        int r0 = bm + wm + mi * 16 + g;
        int r1 = r0 + 8;
#pragma unroll
        for (int ni = 0; ni < 8; ni++) {
            int col = bn + wn + ni * 8 + tg * 2;
            if (r0 < M)
                *(__half2*)&C[(size_t)r0 * Ntot + col] =
                    __floats2half2_rn(acc[mi][ni][0], acc[mi][ni][1]);
            if (r1 < M)
                *(__half2*)&C[(size_t)r1 * Ntot + col] =
                    __floats2half2_rn(acc[mi][ni][2], acc[mi][ni][3]);
        }
    }

    // fused attention projections (fp32-exact)
    const int hw = Ntot / H;
    const int gcol0 = bn + wn;
    const int hh = gcol0 / hw;
    float pa[2][2], pd[2][2];
#pragma unroll
    for (int mi = 0; mi < 2; mi++) { pa[mi][0] = pa[mi][1] = pd[mi][0] = pd[mi][1] = 0.f; }
#pragma unroll
    for (int ni = 0; ni < 8; ni++) {
        int gc = gcol0 + ni * 8 + tg * 2;
        int ch = gc - hh * hw;
        float s0 = attS[hh * hw + ch], s1 = attS[hh * hw + ch + 1];
        float d0 = attD[hh * hw + ch], d1 = attD[hh * hw + ch + 1];
#pragma unroll
        for (int mi = 0; mi < 2; mi++) {
            pa[mi][0] += acc[mi][ni][0] * s0 + acc[mi][ni][1] * s1;
            pd[mi][0] += acc[mi][ni][0] * d0 + acc[mi][ni][1] * d1;
            pa[mi][1] += acc[mi][ni][2] * s0 + acc[mi][ni][3] * s1;
            pd[mi][1] += acc[mi][ni][2] * d0 + acc[mi][ni][3] * d1;
        }
    }
#pragma unroll
    for (int mi = 0; mi < 2; mi++)
#pragma unroll
        for (int rh = 0; rh < 2; rh++) {
            pa[mi][rh] += __shfl_xor_sync(0xffffffffu, pa[mi][rh], 1);
            pa[mi][rh] += __shfl_xor_sync(0xffffffffu, pa[mi][rh], 2);
            pd[mi][rh] += __shfl_xor_sync(0xffffffffu, pd[mi][rh], 1);
            pd[mi][rh] += __shfl_xor_sync(0xffffffffu, pd[mi][rh], 2);
        }
    if (hw == 64) {
        if (tg == 0) {
#pragma unroll
            for (int mi = 0; mi < 2; mi++)
#pragma unroll
                for (int rh = 0; rh < 2; rh++) {
                    int r = bm + wm + mi * 16 + g + rh * 8;
                    if (r < M) {
                        aS[(size_t)r * H + hh] = pa[mi][rh];
                        aD[(size_t)r * H + hh] = pd[mi][rh];
                    }
                }
        }
    } else {
        int half = wid >> 2;
        if (tg == 0) {
#pragma unroll
            for (int mi = 0; mi < 2; mi++)
#pragma unroll
                for (int rh = 0; rh < 2; rh++) {
                    int r = wm + mi * 16 + g + rh * 8;
                    redA[half * 128 + r] = pa[mi][rh];
                    redD[half * 128 + r] = pd[mi][rh];
                }
        }
        __syncthreads();
        if (tid < 128) {
            int r = bm + tid;
            if (r < M) {
                aS[r] = redA[tid] + redA[128 + tid];
                aD[r] = redD[tid] + redD[128 + tid];
            }
        }
    }
}

// ---------------- fused one-pass segment-softmax + aggregation -------------
__global__ void gatagg1_kernel(const float* __restrict__ b1, int N) {
    int n = blockIdx.x;
    int t = threadIdx.x;
    int h = t >> 4;
    if (t == 0) g_cursor[n] = 0;
    int start = g_rowstart[n], end = g_rowstart[n + 1];
    __shared__ int ssrc[32];
    __shared__ float sex[32 * 8];
    float adst = g_adst1[n * 8 + h];
    float den = 0.f;
    float4 acc = make_float4(0.f, 0.f, 0.f, 0.f);
    for (int c0 = start; c0 < end; c0 += 32) {
        int cnt = min(32, end - c0);
        if (t < cnt) ssrc[t] = g_csrc[c0 + t];
        __syncthreads();
        {
            int j0 = t & 15;
#pragma unroll
            for (int q = 0; q < 2; q++) {
                int j = j0 + q * 16;
                if (j < cnt) {
                    int s = ssrc[j];
                    float v = g_asrc1[s * 8 + h] + adst;
                    v = (v >= 0.f) ? v : 0.2f * v;
                    sex[j * 8 + h] = __expf(v);
                }
            }
        }
        __syncthreads();
#pragma unroll 4
        for (int j = 0; j < cnt; j++) {
            float ex = sex[j * 8 + h];
            int s = ssrc[j];
            uint2 u = *(const uint2*)&g_h1h[(size_t)s * 512 + t * 4];
            float2 f0 = __half22float2(*(__half2*)&u.x);
            float2 f1 = __half22float2(*(__half2*)&u.y);
            den += ex;
            acc.x += ex * f0.x; acc.y += ex * f0.y;
            acc.z += ex * f1.x; acc.w += ex * f1.y;
        }
        __syncthreads();
    }
    float inv = 1.f / (den + 1e-16f);
    float4 bb = *(const float4*)&b1[t * 4];
    float o[4];
    o[0] = fmaxf(fmaf(acc.x, inv, bb.x), 0.f);
    o[1] = fmaxf(fmaf(acc.y, inv, bb.y), 0.f);
    o[2] = fmaxf(fmaf(acc.z, inv, bb.z), 0.f);
    o[3] = fmaxf(fmaf(acc.w, inv, bb.w), 0.f);
    uint32_t ph[2], pl[2];
#pragma unroll
    for (int k = 0; k < 2; k++) {
        __nv_bfloat16 h0 = __float2bfloat16(o[2 * k]);
        __nv_bfloat16 h1v = __float2bfloat16(o[2 * k + 1]);
        __nv_bfloat16 l0 = __float2bfloat16(o[2 * k] - __bfloat162float(h0));
        __nv_bfloat16 l1 = __float2bfloat16(o[2 * k + 1] - __bfloat162float(h1v));
        ph[k] = (uint32_t)__bfloat16_as_ushort(h0) | ((uint32_t)__bfloat16_as_ushort(h1v) << 16);
        pl[k] = (uint32_t)__bfloat16_as_ushort(l0) | ((uint32_t)__bfloat16_as_ushort(l1) << 16);
    }
    size_t o4 = (size_t)n * 512 + t * 4;
    *(uint2*)&g_o1hi[o4] = make_uint2(ph[0], ph[1]);
    *(uint2*)&g_o1lo[o4] = make_uint2(pl[0], pl[1]);
}

// layer2 agg + fused attention pooling (H=1): warp per node.
__global__ void gatagg2_kernel(const float* __restrict__ b2,
                               const int* __restrict__ batch,
                               const float* __restrict__ wA, const float* __restrict__ bA,
                               const float* __restrict__ wM, const float* __restrict__ bM,
                               int N) {
    int n = blockIdx.x * 8 + (threadIdx.x >> 5);
    if (n >= N) return;
    int lane = threadIdx.x & 31;
    int start = g_rowstart[n], end = g_rowstart[n + 1];
    float adst = g_adst2[n];
    float den = 0.f;
    float4 acc = make_float4(0.f, 0.f, 0.f, 0.f);
    for (int c0 = start; c0 < end; c0 += 32) {
        int cnt = min(32, end - c0);
        int s = 0; float ex = 0.f;
        if (lane < cnt) {
            s = g_csrc[c0 + lane];
            float v = g_asrc2[s] + adst;
            v = (v >= 0.f) ? v : 0.2f * v;
            ex = __expf(v);
        }
#pragma unroll 4
        for (int j = 0; j < cnt; j++) {
            int bs = __shfl_sync(0xffffffffu, s, j);
            float bex = __shfl_sync(0xffffffffu, ex, j);
            uint2 u = *(const uint2*)&g_h2h[(size_t)bs * 128 + lane * 4];
            float2 f0 = __half22float2(*(__half2*)&u.x);
            float2 f1 = __half22float2(*(__half2*)&u.y);
            den += bex;
            acc.x += bex * f0.x; acc.y += bex * f0.y;
            acc.z += bex * f1.x; acc.w += bex * f1.y;
        }
    }
    float inv = 1.f / (den + 1e-16f);
    float4 bb = *(const float4*)&b2[lane * 4];
    float4 o;
    o.x = fmaxf(fmaf(acc.x, inv, bb.x), 0.f);
    o.y = fmaxf(fmaf(acc.y, inv, bb.y), 0.f);
    o.z = fmaxf(fmaf(acc.z, inv, bb.z), 0.f);
    o.w = fmaxf(fmaf(acc.w, inv, bb.w), 0.f);

    float4 wAv = *(const float4*)&wA[lane * 4];
    float4 wMv = *(const float4*)&wM[lane * 4];
    float sA = o.x * wAv.x + o.y * wAv.y + o.z * wAv.z + o.w * wAv.w;
    float sM = o.x * wMv.x + o.y * wMv.y + o.z * wMv.z + o.w * wMv.w;
#pragma unroll
    for (int off = 16; off > 0; off >>= 1) {
        sA += __shfl_xor_sync(0xffffffffu, sA, off);
        sM += __shfl_xor_sync(0xffffffffu, sM, off);
    }
    float wgt = (sA + bA[0]) * (1.f / (1.f + __expf(-(sM + bM[0]))));
    float* pp = &g_pooled[batch[n] * 128 + lane * 4];
    atomicAdd(pp + 0, o.x * wgt);
    atomicAdd(pp + 1, o.y * wgt);
    atomicAdd(pp + 2, o.z * wgt);
    atomicAdd(pp + 3, o.w * wgt);
}

// ---------------- final projection ------------------------------------------
__global__ void final_kernel(const float* __restrict__ Wo,
                             const float* __restrict__ bo,
                             float* __restrict__ out) {
    int i = threadIdx.x;
    int g = i >> 1, o = i & 1;
    float s = 0.f;
#pragma unroll 4
    for (int k = 0; k < 128; k++)
        s += g_pooled[g * 128 + k] * Wo[o * 128 + k];
    out[i] = s + bo[o];
}

// ---------------- launch ----------------------------------------------------
extern "C" void kernel_launch(void* const* d_in, const int* in_sizes, int n_in,
                              void* d_out, int out_size) {
    const float* x      = (const float*)d_in[0];
    const int*   ei     = (const int*)d_in[1];
    const int*   batch  = (const int*)d_in[2];
    const float* W1     = (const float*)d_in[3];
    const float* as1    = (const float*)d_in[4];
    const float* ad1    = (const float*)d_in[5];
    const float* b1     = (const float*)d_in[6];
    const float* W2     = (const float*)d_in[7];
    const float* as2    = (const float*)d_in[8];
    const float* ad2    = (const float*)d_in[9];
    const float* b2     = (const float*)d_in[10];
    const float* w_attn = (const float*)d_in[11];
    const float* b_attn = (const float*)d_in[12];
    const float* w_mask = (const float*)d_in[13];
    const float* b_mask = (const float*)d_in[14];
    const float* W_out  = (const float*)d_in[15];
    const float* b_out  = (const float*)d_in[16];
    float* out = (float*)d_out;

    int N = in_sizes[0] / 128;
    int E = in_sizes[1] / 2;
    int ET = N + E;

    __half *p_h1, *p_h2;
    float *p_as1, *p_ad1, *p_as2, *p_ad2;
    __nv_bfloat16 *p_xhi, *p_xlo, *p_o1hi, *p_o1lo, *p_w1hi, *p_w1lo, *p_w2hi, *p_w2lo;
    cudaGetSymbolAddress((void**)&p_h1, g_h1h);
    cudaGetSymbolAddress((void**)&p_h2, g_h2h);
    cudaGetSymbolAddress((void**)&p_as1, g_asrc1);
    cudaGetSymbolAddress((void**)&p_ad1, g_adst1);
    cudaGetSymbolAddress((void**)&p_as2, g_asrc2);
    cudaGetSymbolAddress((void**)&p_ad2, g_adst2);
    cudaGetSymbolAddress((void**)&p_xhi, g_xhi);
    cudaGetSymbolAddress((void**)&p_xlo, g_xlo);
    cudaGetSymbolAddress((void**)&p_o1hi, g_o1hi);
    cudaGetSymbolAddress((void**)&p_o1lo, g_o1lo);
    cudaGetSymbolAddress((void**)&p_w1hi, g_w1hi);
    cudaGetSymbolAddress((void**)&p_w1lo, g_w1lo);
    cudaGetSymbolAddress((void**)&p_w2hi, g_w2hi);
    cudaGetSymbolAddress((void**)&p_w2lo, g_w2lo);

    cudaFuncSetAttribute(gemm_kernel, cudaFuncAttributeMaxDynamicSharedMemorySize, GEMM_SMEM);

    static cudaStream_t s_side = nullptr;
    static cudaEvent_t s_evF = nullptr, s_evJ = nullptr;
    if (s_side == nullptr) {
        cudaStreamCreateWithFlags(&s_side, cudaStreamNonBlocking);
        cudaEventCreateWithFlags(&s_evF, cudaEventDisableTiming);
        cudaEventCreateWithFlags(&s_evJ, cudaEventDisableTiming);
    }

    int mtiles = (N + 127) / 128;

    // ---- fork: CSR build on side stream ----
    cudaEventRecord(s_evF, 0);
    cudaStreamWaitEvent(s_side, s_evF, 0);
    count_kernel<<<(ET + 255) / 256, 256, 0, s_side>>>(ei, E, N);
    scan_kernel<<<1, 1024, 0, s_side>>>(N, ET);
    scatter_kernel<<<(ET + 255) / 256, 256, 0, s_side>>>(ei, E, N);
    cudaEventRecord(s_evJ, s_side);

    // ---- main stream: merged split + gemm1 ----
    {
        int n0 = N * 128, n1 = 512 * 128, n2 = 128 * 512;
        int tot8 = (n0 + n1 + n2) / 8;
        split3_kernel<<<(tot8 + 255) / 256, 256>>>(x, p_xhi, p_xlo, n0,
                                                   W1, p_w1hi, p_w1lo, n1,
                                                   W2, p_w2hi, p_w2lo, n2);
    }
    {
        dim3 grid(4, mtiles);
        gemm_kernel<<<grid, 256, GEMM_SMEM>>>(p_xhi, p_xlo, p_w1hi, p_w1lo, p_h1,
                                              N, 512, 128, as1, ad1, p_as1, p_ad1, 8);
    }

    // ---- join CSR before the gather ----
    cudaStreamWaitEvent(0, s_evJ, 0);

    gatagg1_kernel<<<N, 128>>>(b1, N);

    {
        dim3 grid(1, mtiles);
        gemm_kernel<<<grid, 256, GEMM_SMEM>>>(p_o1hi, p_o1lo, p_w2hi, p_w2lo, p_h2,
                                              N, 128, 512, as2, ad2, p_as2, p_ad2, 1);
    }
    gatagg2_kernel<<<(N + 7) / 8, 256>>>(b2, batch, w_attn, b_attn, w_mask, b_mask, N);

    final_kernel<<<1, 512>>>(W_out, b_out, out);
}